// round 5
// baseline (speedup 1.0000x reference)
#include <cuda_runtime.h>
#include <cuda_bf16.h>
#include <cstdint>

// Problem constants
#define Bsz 512
#define Dd  256
#define Kq  65536
#define Cc  1000
#define Cpad 1024
#define T_SUPf 0.07f
#define T_DCf  0.1f
#define LSm  0.1f
#define EPSf 1e-8f
#define SPLIT 8

// -------- scratch (static device globals) ----------
__device__ float g_sim[(size_t)512 * Kq];
__device__ __align__(16) __nv_bfloat16 g_Ehi[(size_t)512 * Kq];
__device__ __align__(16) __nv_bfloat16 g_Elo[(size_t)512 * Kq];
__device__ __align__(16) __nv_bfloat16 g_Ahi[(size_t)1024 * Dd];
__device__ __align__(16) __nv_bfloat16 g_Alo[(size_t)1024 * Dd];
__device__ __align__(16) __nv_bfloat16 g_QThi[(size_t)Kq * Dd];
__device__ __align__(16) __nv_bfloat16 g_QTlo[(size_t)Kq * Dd];
__device__ __align__(16) __nv_bfloat16 g_Phi[(size_t)Cpad * Kq];
__device__ __align__(16) __nv_bfloat16 g_Plo[(size_t)Cpad * Kq];
__device__ float g_psum[(size_t)512 * 2048];
__device__ float g_part[(size_t)SPLIT * 512 * Cpad];
__device__ float g_invZ[512];
__device__ float g_row_supin[512];
__device__ float g_row_fc[512];
__device__ float g_row_dc[512];
__device__ int   g_is64;

// ---------------- helpers ----------------
__device__ __forceinline__ uint32_t smem_u32(const void* p) {
    uint32_t a;
    asm("{ .reg .u64 t; cvta.to.shared.u64 t, %1; cvt.u32.u64 %0, t; }" : "=r"(a) : "l"(p));
    return a;
}
__device__ __forceinline__ void cp16(uint32_t dst, const void* src) {
    asm volatile("cp.async.cg.shared.global [%0], [%1], 16;\n" :: "r"(dst), "l"(src));
}
#define CPCOMMIT() asm volatile("cp.async.commit_group;\n" ::: "memory")

__device__ __forceinline__ void ldsm4(uint32_t& r0, uint32_t& r1, uint32_t& r2,
                                      uint32_t& r3, uint32_t addr) {
    asm volatile("ldmatrix.sync.aligned.m8n8.x4.shared.b16 {%0,%1,%2,%3}, [%4];"
                 : "=r"(r0), "=r"(r1), "=r"(r2), "=r"(r3) : "r"(addr));
}

__device__ __forceinline__ void mma_bf16(float* c, uint32_t a0, uint32_t a1,
                                         uint32_t a2, uint32_t a3,
                                         uint32_t b0, uint32_t b1) {
    asm volatile(
        "mma.sync.aligned.m16n8k16.row.col.f32.bf16.bf16.f32 "
        "{%0,%1,%2,%3}, {%4,%5,%6,%7}, {%8,%9}, {%0,%1,%2,%3};\n"
        : "+f"(c[0]), "+f"(c[1]), "+f"(c[2]), "+f"(c[3])
        : "r"(a0), "r"(a1), "r"(a2), "r"(a3), "r"(b0), "r"(b1));
}

// split two fp32 into packed bf16 hi/lo words (elem0 in low half)
__device__ __forceinline__ void split2(float f0, float f1, uint32_t& hi, uint32_t& lo) {
    __nv_bfloat16 h0 = __float2bfloat16(f0), h1 = __float2bfloat16(f1);
    float r0 = f0 - __bfloat162float(h0);
    float r1 = f1 - __bfloat162float(h1);
    __nv_bfloat16 l0 = __float2bfloat16(r0), l1 = __float2bfloat16(r1);
    hi = ((uint32_t)__bfloat16_as_ushort(h1) << 16) | (uint32_t)__bfloat16_as_ushort(h0);
    lo = ((uint32_t)__bfloat16_as_ushort(l1) << 16) | (uint32_t)__bfloat16_as_ushort(l0);
}

__device__ __forceinline__ unsigned fmap(float f) {
    unsigned u = __float_as_uint(f);
    return (u & 0x80000000u) ? ~u : (u | 0x80000000u);
}

// ---------------------------------------------------------------------------
__global__ void detect_kernel(const int* __restrict__ qlabel_raw) {
    if (threadIdx.x == 0 && blockIdx.x == 0) {
        int is64 = 1;
        for (int i = 0; i < 4096; i++) {
            if (qlabel_raw[2 * i + 1] != 0) { is64 = 0; break; }
        }
        g_is64 = is64;
    }
}
__device__ __forceinline__ long long load_label(const void* p, int i) {
    if (g_is64) return ((const long long*)p)[i];
    return (long long)((const int*)p)[i];
}

// ---------------------------------------------------------------------------
// convA / convQ / convP: fp32 -> split bf16 (unchanged, all near roofline)
// ---------------------------------------------------------------------------
__global__ void __launch_bounds__(256) convA_kernel(const float* __restrict__ nq,
                                                    const float* __restrict__ kf) {
    size_t i = ((size_t)blockIdx.x * 256 + threadIdx.x) * 4;
    const size_t half = (size_t)512 * Dd;
    const float* src = (i < half) ? (nq + i) : (kf + (i - half));
    float4 v = *(const float4*)src;
    uint32_t h0, l0, h1, l1;
    split2(v.x, v.y, h0, l0);
    split2(v.z, v.w, h1, l1);
    *(uint2*)(g_Ahi + i) = make_uint2(h0, h1);
    *(uint2*)(g_Alo + i) = make_uint2(l0, l1);
}

__global__ void __launch_bounds__(256) convQ_kernel(const float* __restrict__ Q) {
    __shared__ float s[32][65];
    const int n0 = blockIdx.x * 32, d0 = blockIdx.y * 64;
    const int t = threadIdx.x;
    const int nl = t & 31, dl = t >> 5;
    #pragma unroll
    for (int i = 0; i < 8; i++) {
        int d = i * 8 + dl;
        s[nl][d] = Q[(size_t)(d0 + d) * Kq + n0 + nl];
    }
    __syncthreads();
    const int n = t >> 3, dq = (t & 7) * 8;
    uint32_t hi[4], lo[4];
    #pragma unroll
    for (int j = 0; j < 4; j++)
        split2(s[n][dq + 2 * j], s[n][dq + 2 * j + 1], hi[j], lo[j]);
    size_t off = (size_t)(n0 + n) * Dd + d0 + dq;
    *(uint4*)(g_QThi + off) = make_uint4(hi[0], hi[1], hi[2], hi[3]);
    *(uint4*)(g_QTlo + off) = make_uint4(lo[0], lo[1], lo[2], lo[3]);
}

__global__ void __launch_bounds__(256) convP_kernel(const float* __restrict__ P) {
    const int c = blockIdx.y;
    const size_t k = (size_t)blockIdx.x * 2048 + threadIdx.x * 8;
    size_t off = (size_t)c * Kq + k;
    uint32_t hi[4], lo[4];
    if (c < Cc) {
        float4 v0 = *(const float4*)(P + off);
        float4 v1 = *(const float4*)(P + off + 4);
        split2(v0.x, v0.y, hi[0], lo[0]);
        split2(v0.z, v0.w, hi[1], lo[1]);
        split2(v1.x, v1.y, hi[2], lo[2]);
        split2(v1.z, v1.w, hi[3], lo[3]);
    } else {
        hi[0] = hi[1] = hi[2] = hi[3] = 0u;
        lo[0] = lo[1] = lo[2] = lo[3] = 0u;
    }
    *(uint4*)(g_Phi + off) = make_uint4(hi[0], hi[1], hi[2], hi[3]);
    *(uint4*)(g_Plo + off) = make_uint4(lo[0], lo[1], lo[2], lo[3]);
}

// ---------------------------------------------------------------------------
// GEMM core v2: CTA 128x128, kc=32, 3-stage cp.async pipeline, ldmatrix.
// smem row = 128 B: [hi k0..31 | lo k0..31], XOR-8 swizzle on 16B chunks.
// Stage = A(16 KB) + B(16 KB) = 32 KB; 3 stages = 96 KB.
// Warps 2(M) x 4(N), warp tile 64x32, acc[4][4][4].
// ---------------------------------------------------------------------------
#define STG_B 32768

__device__ __forceinline__ void load_stage(uint32_t sbase, int buf,
    const __nv_bfloat16* Ah, const __nv_bfloat16* Al,
    const __nv_bfloat16* Bh, const __nv_bfloat16* Bl,
    size_t kstride, int kc, int tid)
{
    const uint32_t sA = sbase + (uint32_t)buf * STG_B;
    const uint32_t sB = sA + 16384;
    #pragma unroll
    for (int i = 0; i < 4; i++) {
        int idx = tid * 4 + i;
        int row = idx >> 3, c = idx & 7;
        uint32_t off = (uint32_t)(row * 128) + (uint32_t)((c ^ (row & 7)) * 16);
        size_t gofs = (size_t)row * kstride + kc + (c & 3) * 8;
        cp16(sA + off, ((c < 4) ? Ah : Al) + gofs);
        cp16(sB + off, ((c < 4) ? Bh : Bl) + gofs);
    }
}

__device__ __forceinline__ void compute_stage(uint32_t sbase, int buf,
    float acc[4][4][4], int wm, int wn, int lane)
{
    const uint32_t sA = sbase + (uint32_t)buf * STG_B;
    const uint32_t sB = sA + 16384;
    const int lrow = (lane & 7) | (((lane >> 3) & 1) << 3);  // 0..15
    const int lsel = lane >> 4;                               // 0..1
    #pragma unroll
    for (int h = 0; h < 2; h++) {
        const int ch = 2 * h + lsel;
        uint32_t bh[2][4], bl[2][4];
        #pragma unroll
        for (int t2 = 0; t2 < 2; t2++) {
            int row = wn * 32 + t2 * 16 + lrow;
            uint32_t a1 = sB + row * 128 + ((ch ^ (row & 7)) * 16);
            uint32_t a2 = sB + row * 128 + (((ch + 4) ^ (row & 7)) * 16);
            ldsm4(bh[t2][0], bh[t2][1], bh[t2][2], bh[t2][3], a1);
            ldsm4(bl[t2][0], bl[t2][1], bl[t2][2], bl[t2][3], a2);
        }
        #pragma unroll
        for (int m = 0; m < 4; m++) {
            int row = wm * 64 + m * 16 + lrow;
            uint32_t a1 = sA + row * 128 + ((ch ^ (row & 7)) * 16);
            uint32_t a2 = sA + row * 128 + (((ch + 4) ^ (row & 7)) * 16);
            uint32_t ah[4], al[4];
            ldsm4(ah[0], ah[1], ah[2], ah[3], a1);
            ldsm4(al[0], al[1], al[2], al[3], a2);
            #pragma unroll
            for (int n = 0; n < 4; n++) {
                int t2 = n >> 1, nn = n & 1;
                uint32_t b0h = bh[t2][nn], b1h = bh[t2][nn + 2];
                uint32_t b0l = bl[t2][nn], b1l = bl[t2][nn + 2];
                mma_bf16(acc[m][n], ah[0], ah[1], ah[2], ah[3], b0h, b1h);
                mma_bf16(acc[m][n], ah[0], ah[1], ah[2], ah[3], b0l, b1l);
                mma_bf16(acc[m][n], al[0], al[1], al[2], al[3], b0h, b1h);
            }
        }
    }
}

// ---------------------------------------------------------------------------
// GEMM1: [A;..](1024x256) @ QT^T -> sim (mt<4) / E (mt>=4)
// grid (nt=512, mt=8), 256 threads.
// ---------------------------------------------------------------------------
__global__ void __launch_bounds__(256) gemm1_mma() {
    extern __shared__ __align__(16) uint32_t sm[];
    const int nt = blockIdx.x;
    const int mt = blockIdx.y;
    const int tid = threadIdx.x;
    const int lane = tid & 31, wid = tid >> 5;
    const int wm = wid >> 2, wn = wid & 3;
    const int g = lane >> 2, tig = lane & 3;
    const uint32_t sbase = smem_u32(sm);

    const __nv_bfloat16* Ah = g_Ahi + (size_t)mt * 128 * Dd;
    const __nv_bfloat16* Al = g_Alo + (size_t)mt * 128 * Dd;
    const __nv_bfloat16* Bh = g_QThi + (size_t)nt * 128 * Dd;
    const __nv_bfloat16* Bl = g_QTlo + (size_t)nt * 128 * Dd;

    float acc[4][4][4] = {};
    const int NS = Dd / 32;   // 8

    load_stage(sbase, 0, Ah, Al, Bh, Bl, Dd, 0, tid);
    CPCOMMIT();
    load_stage(sbase, 1, Ah, Al, Bh, Bl, Dd, 32, tid);
    CPCOMMIT();
    for (int s = 0; s < NS; s++) {
        if (s + 1 < NS) asm volatile("cp.async.wait_group 1;\n" ::: "memory");
        else            asm volatile("cp.async.wait_group 0;\n" ::: "memory");
        __syncthreads();
        if (s + 2 < NS) {
            load_stage(sbase, (s + 2) % 3, Ah, Al, Bh, Bl, Dd, (s + 2) * 32, tid);
            CPCOMMIT();
        }
        compute_stage(sbase, s % 3, acc, wm, wn, lane);
    }

    // epilogue
    const int rbase = mt * 128 + wm * 64;
    const int col = nt * 128 + wn * 32;
    if (mt < 4) {
        #pragma unroll
        for (int m = 0; m < 4; m++) {
            int r0 = rbase + m * 16 + g;
            #pragma unroll
            for (int n = 0; n < 4; n++) {
                int c = col + n * 8 + tig * 2;
                *(float2*)&g_sim[(size_t)r0 * Kq + c] = make_float2(acc[m][n][0], acc[m][n][1]);
                *(float2*)&g_sim[(size_t)(r0 + 8) * Kq + c] = make_float2(acc[m][n][2], acc[m][n][3]);
            }
        }
    } else {
        #pragma unroll
        for (int m = 0; m < 4; m++) {
            int b0 = rbase - 512 + m * 16 + g;
            float s0 = 0.f, s1 = 0.f;
            #pragma unroll
            for (int n = 0; n < 4; n++) {
                int c = col + n * 8 + tig * 2;
                float e0 = __expf(acc[m][n][0] * (1.0f / T_DCf));
                float e1 = __expf(acc[m][n][1] * (1.0f / T_DCf));
                float e2 = __expf(acc[m][n][2] * (1.0f / T_DCf));
                float e3 = __expf(acc[m][n][3] * (1.0f / T_DCf));
                uint32_t h, l;
                split2(e0, e1, h, l);
                *(uint32_t*)&g_Ehi[(size_t)b0 * Kq + c] = h;
                *(uint32_t*)&g_Elo[(size_t)b0 * Kq + c] = l;
                split2(e2, e3, h, l);
                *(uint32_t*)&g_Ehi[(size_t)(b0 + 8) * Kq + c] = h;
                *(uint32_t*)&g_Elo[(size_t)(b0 + 8) * Kq + c] = l;
                s0 += e0 + e1;
                s1 += e2 + e3;
            }
            s0 += __shfl_xor_sync(0xffffffffu, s0, 1);
            s0 += __shfl_xor_sync(0xffffffffu, s0, 2);
            s1 += __shfl_xor_sync(0xffffffffu, s1, 1);
            s1 += __shfl_xor_sync(0xffffffffu, s1, 2);
            if (tig == 0) {
                g_psum[(size_t)b0 * 2048 + nt * 4 + wn] = s0;
                g_psum[(size_t)(b0 + 8) * 2048 + nt * 4 + wn] = s1;
            }
        }
    }
}

// ---------------------------------------------------------------------------
// GEMM2 (split-K): part[sp] = E(512x65536) @ Pbf^T
// grid (nt=8, mt=4, sp=8), 256 threads.
// ---------------------------------------------------------------------------
__global__ void __launch_bounds__(256) gemm2_mma() {
    extern __shared__ __align__(16) uint32_t sm[];
    const int nt = blockIdx.x;
    const int mt = blockIdx.y;
    const int sp = blockIdx.z;
    const int tid = threadIdx.x;
    const int lane = tid & 31, wid = tid >> 5;
    const int wm = wid >> 2, wn = wid & 3;
    const int g = lane >> 2, tig = lane & 3;
    const uint32_t sbase = smem_u32(sm);

    const size_t k0 = (size_t)sp * (Kq / SPLIT);
    const __nv_bfloat16* Ah = g_Ehi + (size_t)mt * 128 * Kq + k0;
    const __nv_bfloat16* Al = g_Elo + (size_t)mt * 128 * Kq + k0;
    const __nv_bfloat16* Bh = g_Phi + (size_t)nt * 128 * Kq + k0;
    const __nv_bfloat16* Bl = g_Plo + (size_t)nt * 128 * Kq + k0;

    float acc[4][4][4] = {};
    const int NS = (Kq / SPLIT) / 32;   // 256

    load_stage(sbase, 0, Ah, Al, Bh, Bl, Kq, 0, tid);
    CPCOMMIT();
    load_stage(sbase, 1, Ah, Al, Bh, Bl, Kq, 32, tid);
    CPCOMMIT();
    for (int s = 0; s < NS; s++) {
        if (s + 1 < NS) asm volatile("cp.async.wait_group 1;\n" ::: "memory");
        else            asm volatile("cp.async.wait_group 0;\n" ::: "memory");
        __syncthreads();
        if (s + 2 < NS) {
            load_stage(sbase, (s + 2) % 3, Ah, Al, Bh, Bl, Kq, (s + 2) * 32, tid);
            CPCOMMIT();
        }
        compute_stage(sbase, s % 3, acc, wm, wn, lane);
    }

    // epilogue: split-K partials
    #pragma unroll
    for (int m = 0; m < 4; m++) {
        int b = mt * 128 + wm * 64 + m * 16 + g;
        #pragma unroll
        for (int n = 0; n < 4; n++) {
            int c = nt * 128 + wn * 32 + n * 8 + tig * 2;
            *(float2*)&g_part[((size_t)sp * 512 + b) * Cpad + c] =
                make_float2(acc[m][n][0], acc[m][n][1]);
            *(float2*)&g_part[((size_t)sp * 512 + b + 8) * Cpad + c] =
                make_float2(acc[m][n][2], acc[m][n][3]);
        }
    }
}

// ---------------------------------------------------------------------------
// invz / supcon / fcdc / finalize (unchanged)
// ---------------------------------------------------------------------------
__global__ void __launch_bounds__(256) invz_kernel() {
    const int b = blockIdx.x;
    const int tid = threadIdx.x;
    float s = 0.f;
    for (int i = tid; i < 2048; i += 256) s += g_psum[(size_t)b * 2048 + i];
    __shared__ float red[256];
    red[tid] = s;
    __syncthreads();
    for (int o = 128; o > 0; o >>= 1) {
        if (tid < o) red[tid] += red[tid + o];
        __syncthreads();
    }
    if (tid == 0) g_invZ[b] = 1.0f / red[0];
}

#define MAXTIES 2048
__global__ void __launch_bounds__(256) supcon_kernel(
    const void* __restrict__ qlabel,
    const void* __restrict__ target,
    const int*  __restrict__ knnk)
{
    const int b = blockIdx.x;
    const float* row = g_sim + (size_t)b * Kq;
    const int tid = threadIdx.x;
    const int NT = 256;
    const int kneed = knnk[0];

    __shared__ unsigned hist[256];
    __shared__ unsigned s_prefix, s_desired;
    __shared__ int s_ties;
    __shared__ int tie_idx[MAXTIES];
    __shared__ float ra[256], rp[256];

    if (tid == 0) { s_prefix = 0; s_desired = (unsigned)kneed; }
    __syncthreads();

    for (int pass = 0; pass < 4; pass++) {
        const int shift = 24 - pass * 8;
        for (int i = tid; i < 256; i += NT) hist[i] = 0;
        __syncthreads();
        const unsigned pref = s_prefix;
        for (int k = tid; k < Kq; k += NT) {
            unsigned u = fmap(row[k]);
            bool ok = (pass == 0) || ((u >> (shift + 8)) == pref);
            if (ok) atomicAdd(&hist[(u >> shift) & 255u], 1u);
        }
        __syncthreads();
        if (tid == 0) {
            unsigned des = s_desired;
            for (int bin = 255; bin >= 0; bin--) {
                unsigned c = hist[bin];
                if (c >= des) {
                    s_prefix = (pref << 8) | (unsigned)bin;
                    s_desired = des;
                    break;
                }
                des -= c;
            }
        }
        __syncthreads();
    }

    const unsigned u200 = s_prefix;
    const unsigned des = s_desired;
    if (tid == 0) s_ties = 0;
    __syncthreads();

    float sa = 0.f, sp = 0.f;
    const long long tgt = load_label(target, b);
    for (int k = tid; k < Kq; k += NT) {
        float sv = row[k];
        unsigned u = fmap(sv);
        if (u > u200) {
            float e = __expf(sv * (1.0f / T_SUPf));
            sa += e;
            if (load_label(qlabel, k) == tgt) sp += e;
        } else if (u == u200) {
            int p = atomicAdd(&s_ties, 1);
            if (p < MAXTIES) tie_idx[p] = k;
        }
    }
    ra[tid] = sa; rp[tid] = sp;
    __syncthreads();
    for (int o = 128; o > 0; o >>= 1) {
        if (tid < o) { ra[tid] += ra[tid + o]; rp[tid] += rp[tid + o]; }
        __syncthreads();
    }

    if (tid == 0) {
        float SA = ra[0], SP = rp[0];
        int t = min(s_ties, MAXTIES);
        for (int i = 1; i < t; i++) {
            int v = tie_idx[i]; int j = i - 1;
            while (j >= 0 && tie_idx[j] > v) { tie_idx[j + 1] = tie_idx[j]; j--; }
            tie_idx[j + 1] = v;
        }
        int take = min((int)des, t);
        for (int i = 0; i < take; i++) {
            int k = tie_idx[i];
            float e = __expf(row[k] * (1.0f / T_SUPf));
            SA += e;
            if (load_label(qlabel, k) == tgt) SP += e;
        }
        float gt = SP / SA;
        g_row_supin[b] = (gt > EPSf) ? (-__logf(gt)) : 0.0f;
    }
}

__global__ void __launch_bounds__(256) fcdc_kernel(
    const float* __restrict__ qlog,
    const void* __restrict__ target)
{
    const int b = blockIdx.x;
    const int tid = threadIdx.x;
    const float* q = qlog + (size_t)b * Cc;
    __shared__ float red[256];

    float mx = -3.4e38f;
    for (int c = tid; c < Cc; c += 256) mx = fmaxf(mx, q[c]);
    red[tid] = mx; __syncthreads();
    for (int o = 128; o > 0; o >>= 1) { if (tid < o) red[tid] = fmaxf(red[tid], red[tid + o]); __syncthreads(); }
    const float Mx = red[0]; __syncthreads();

    float mn = 3.4e38f;
    for (int c = tid; c < Cc; c += 256) mn = fminf(mn, q[c]);
    red[tid] = mn; __syncthreads();
    for (int o = 128; o > 0; o >>= 1) { if (tid < o) red[tid] = fminf(red[tid], red[tid + o]); __syncthreads(); }
    const float Mn = red[0]; __syncthreads();

    float se = 0.f;
    for (int c = tid; c < Cc; c += 256) se += __expf(q[c] - Mx);
    red[tid] = se; __syncthreads();
    for (int o = 128; o > 0; o >>= 1) { if (tid < o) red[tid] += red[tid + o]; __syncthreads(); }
    const float SE = red[0]; __syncthreads();

    const float logZ = __logf(SE);
    const bool qmask = (__expf(Mn - Mx) / SE) > EPSf;
    const float invZk = g_invZ[b];
    const long long t = load_label(target, b);

    float fcs = 0.f, kl = 0.f;
    for (int c = tid; c < Cc; c += 256) {
        float lq = q[c] - Mx - logZ;
        float oh = (c == (int)t) ? (1.0f - LSm) : (LSm / (float)(Cc - 1));
        fcs += oh * lq;
        float ps = 0.f;
        #pragma unroll
        for (int s = 0; s < SPLIT; s++)
            ps += g_part[((size_t)s * 512 + b) * Cpad + c];
        float dct = invZk * ps;
        if (dct > 0.f) kl += dct * (__logf(dct) - lq);
    }
    red[tid] = fcs; __syncthreads();
    for (int o = 128; o > 0; o >>= 1) { if (tid < o) red[tid] += red[tid + o]; __syncthreads(); }
    const float FCS = red[0]; __syncthreads();
    red[tid] = kl; __syncthreads();
    for (int o = 128; o > 0; o >>= 1) { if (tid < o) red[tid] += red[tid + o]; __syncthreads(); }
    if (tid == 0) {
        g_row_fc[b] = qmask ? FCS : 0.f;
        g_row_dc[b] = qmask ? red[0] : 0.f;
    }
}

__global__ void __launch_bounds__(512) finalize_kernel(float* __restrict__ out) {
    const int tid = threadIdx.x;
    __shared__ float r[512];

    r[tid] = g_row_supin[tid]; __syncthreads();
    for (int o = 256; o > 0; o >>= 1) { if (tid < o) r[tid] += r[tid + o]; __syncthreads(); }
    if (tid == 0) out[0] = r[0] / (float)Bsz;
    __syncthreads();

    r[tid] = g_row_fc[tid]; __syncthreads();
    for (int o = 256; o > 0; o >>= 1) { if (tid < o) r[tid] += r[tid + o]; __syncthreads(); }
    if (tid == 0) out[1] = -r[0] / (float)Bsz;
    __syncthreads();

    r[tid] = g_row_dc[tid]; __syncthreads();
    for (int o = 256; o > 0; o >>= 1) { if (tid < o) r[tid] += r[tid + o]; __syncthreads(); }
    if (tid == 0) out[2] = r[0] / (float)Bsz;
}

// ---------------------------------------------------------------------------
extern "C" void kernel_launch(void* const* d_in, const int* in_sizes, int n_in,
                              void* d_out, int out_size)
{
    const float* normq  = (const float*)d_in[0];
    const float* qlog   = (const float*)d_in[1];
    const float* kfeat  = (const float*)d_in[2];
    // d_in[3] = logits_k (unused)
    const float* queue  = (const float*)d_in[4];
    const float* qlp    = (const float*)d_in[5];
    const void*  qlabel = d_in[6];
    const void*  target = d_in[7];
    const int*   knnk   = (const int*)d_in[8];
    float* out = (float*)d_out;

    const int SMEM = 3 * STG_B;  // 96 KB
    cudaFuncSetAttribute(gemm1_mma, cudaFuncAttributeMaxDynamicSharedMemorySize, SMEM);
    cudaFuncSetAttribute(gemm2_mma, cudaFuncAttributeMaxDynamicSharedMemorySize, SMEM);

    detect_kernel<<<1, 32>>>((const int*)qlabel);
    convA_kernel<<<256, 256>>>(normq, kfeat);
    convQ_kernel<<<dim3(2048, 4), 256>>>(queue);
    convP_kernel<<<dim3(32, 1024), 256>>>(qlp);
    gemm1_mma<<<dim3(512, 8), 256, SMEM>>>();
    supcon_kernel<<<512, 256>>>(qlabel, target, knnk);
    invz_kernel<<<512, 256>>>();
    gemm2_mma<<<dim3(8, 4, 8), 256, SMEM>>>();
    fcdc_kernel<<<512, 256>>>(qlog, target);
    finalize_kernel<<<1, 512>>>(out);
    (void)in_sizes; (void)n_in; (void)out_size;
}

// round 6
// speedup vs baseline: 1.3991x; 1.3991x over previous
#include <cuda_runtime.h>
#include <cuda_bf16.h>
#include <cstdint>

// Problem constants
#define Bsz 512
#define Dd  256
#define Kq  65536
#define Cc  1000
#define Cpad 1024
#define T_SUPf 0.07f
#define T_DCf  0.1f
#define LSm  0.1f
#define EPSf 1e-8f
#define SPLIT 8
#define PADW 20   // 16 data words + 4 pad per row

// -------- scratch (static device globals) ----------
__device__ float g_sim[(size_t)512 * Kq];
__device__ __align__(16) __nv_bfloat16 g_Ehi[(size_t)512 * Kq];
__device__ __align__(16) __nv_bfloat16 g_Ahi[(size_t)1024 * Dd];
__device__ __align__(16) __nv_bfloat16 g_Alo[(size_t)1024 * Dd];
__device__ __align__(16) __nv_bfloat16 g_QThi[(size_t)Kq * Dd];
__device__ __align__(16) __nv_bfloat16 g_QTlo[(size_t)Kq * Dd];
__device__ __align__(16) __nv_bfloat16 g_Phi[(size_t)Cpad * Kq];
__device__ __align__(16) __nv_bfloat16 g_Plo[(size_t)Cpad * Kq];
__device__ float g_psum[(size_t)512 * 2048];
__device__ float g_part[(size_t)SPLIT * 512 * Cpad];
__device__ float g_invZ[512];
__device__ float g_row_supin[512];
__device__ float g_row_fc[512];
__device__ float g_row_dc[512];
__device__ int   g_is64;

// ---------------- helpers ----------------
__device__ __forceinline__ uint32_t smem_u32(const void* p) {
    uint32_t a;
    asm("{ .reg .u64 t; cvta.to.shared.u64 t, %1; cvt.u32.u64 %0, t; }" : "=r"(a) : "l"(p));
    return a;
}
__device__ __forceinline__ void cp16(uint32_t dst, const void* src) {
    asm volatile("cp.async.cg.shared.global [%0], [%1], 16;\n" :: "r"(dst), "l"(src));
}
#define CPCOMMIT() asm volatile("cp.async.commit_group;\n" ::: "memory")
#define CPWAIT0()  asm volatile("cp.async.wait_group 0;\n" ::: "memory")

__device__ __forceinline__ void mma_bf16(float* c, uint32_t a0, uint32_t a1,
                                         uint32_t a2, uint32_t a3,
                                         uint32_t b0, uint32_t b1) {
    asm volatile(
        "mma.sync.aligned.m16n8k16.row.col.f32.bf16.bf16.f32 "
        "{%0,%1,%2,%3}, {%4,%5,%6,%7}, {%8,%9}, {%0,%1,%2,%3};\n"
        : "+f"(c[0]), "+f"(c[1]), "+f"(c[2]), "+f"(c[3])
        : "r"(a0), "r"(a1), "r"(a2), "r"(a3), "r"(b0), "r"(b1));
}

// split two fp32 into packed bf16 hi/lo words (elem0 in low half)
__device__ __forceinline__ void split2(float f0, float f1, uint32_t& hi, uint32_t& lo) {
    __nv_bfloat16 h0 = __float2bfloat16(f0), h1 = __float2bfloat16(f1);
    float r0 = f0 - __bfloat162float(h0);
    float r1 = f1 - __bfloat162float(h1);
    __nv_bfloat16 l0 = __float2bfloat16(r0), l1 = __float2bfloat16(r1);
    hi = ((uint32_t)__bfloat16_as_ushort(h1) << 16) | (uint32_t)__bfloat16_as_ushort(h0);
    lo = ((uint32_t)__bfloat16_as_ushort(l1) << 16) | (uint32_t)__bfloat16_as_ushort(l0);
}
__device__ __forceinline__ uint32_t pack_bf16(float f0, float f1) {
    return ((uint32_t)__bfloat16_as_ushort(__float2bfloat16(f1)) << 16)
         | (uint32_t)__bfloat16_as_ushort(__float2bfloat16(f0));
}

__device__ __forceinline__ unsigned fmap(float f) {
    unsigned u = __float_as_uint(f);
    return (u & 0x80000000u) ? ~u : (u | 0x80000000u);
}

// ---------------------------------------------------------------------------
__global__ void detect_kernel(const int* __restrict__ qlabel_raw) {
    if (threadIdx.x == 0 && blockIdx.x == 0) {
        int is64 = 1;
        for (int i = 0; i < 4096; i++) {
            if (qlabel_raw[2 * i + 1] != 0) { is64 = 0; break; }
        }
        g_is64 = is64;
    }
}
__device__ __forceinline__ long long load_label(const void* p, int i) {
    if (g_is64) return ((const long long*)p)[i];
    return (long long)((const int*)p)[i];
}

// ---------------------------------------------------------------------------
// convAQ: fused convA + convQ.
// blocks [0, 8192): queue [256][65536] -> QThi/QTlo [65536][256] transpose+split
// blocks [8192, 8448): [normq;kfeat] (1024x256) -> Ahi/Alo
// ---------------------------------------------------------------------------
__global__ void __launch_bounds__(256) convAQ_kernel(
    const float* __restrict__ nq, const float* __restrict__ kf,
    const float* __restrict__ Q)
{
    const int t = threadIdx.x;
    if (blockIdx.x < 8192) {
        __shared__ float s[32][65];
        const int n0 = (blockIdx.x & 2047) * 32, d0 = (blockIdx.x >> 11) * 64;
        const int nl = t & 31, dl = t >> 5;
        #pragma unroll
        for (int i = 0; i < 8; i++) {
            int d = i * 8 + dl;
            s[nl][d] = Q[(size_t)(d0 + d) * Kq + n0 + nl];
        }
        __syncthreads();
        const int n = t >> 3, dq = (t & 7) * 8;
        uint32_t hi[4], lo[4];
        #pragma unroll
        for (int j = 0; j < 4; j++)
            split2(s[n][dq + 2 * j], s[n][dq + 2 * j + 1], hi[j], lo[j]);
        size_t off = (size_t)(n0 + n) * Dd + d0 + dq;
        *(uint4*)(g_QThi + off) = make_uint4(hi[0], hi[1], hi[2], hi[3]);
        *(uint4*)(g_QTlo + off) = make_uint4(lo[0], lo[1], lo[2], lo[3]);
    } else {
        size_t i = ((size_t)(blockIdx.x - 8192) * 256 + t) * 4;
        const size_t half = (size_t)512 * Dd;
        const float* src = (i < half) ? (nq + i) : (kf + (i - half));
        float4 v = *(const float4*)src;
        uint32_t h0, l0, h1, l1;
        split2(v.x, v.y, h0, l0);
        split2(v.z, v.w, h1, l1);
        *(uint2*)(g_Ahi + i) = make_uint2(h0, h1);
        *(uint2*)(g_Alo + i) = make_uint2(l0, l1);
    }
}

// ---------------------------------------------------------------------------
// convP: P [1000][65536] fp32 -> Phi/Plo [1024][65536] (rows >= 1000 zero)
// ---------------------------------------------------------------------------
__global__ void __launch_bounds__(256) convP_kernel(const float* __restrict__ P) {
    const int c = blockIdx.y;
    const size_t k = (size_t)blockIdx.x * 2048 + threadIdx.x * 8;
    size_t off = (size_t)c * Kq + k;
    uint32_t hi[4], lo[4];
    if (c < Cc) {
        float4 v0 = *(const float4*)(P + off);
        float4 v1 = *(const float4*)(P + off + 4);
        split2(v0.x, v0.y, hi[0], lo[0]);
        split2(v0.z, v0.w, hi[1], lo[1]);
        split2(v1.x, v1.y, hi[2], lo[2]);
        split2(v1.z, v1.w, hi[3], lo[3]);
    } else {
        hi[0] = hi[1] = hi[2] = hi[3] = 0u;
        lo[0] = lo[1] = lo[2] = lo[3] = 0u;
    }
    *(uint4*)(g_Phi + off) = make_uint4(hi[0], hi[1], hi[2], hi[3]);
    *(uint4*)(g_Plo + off) = make_uint4(lo[0], lo[1], lo[2], lo[3]);
}

// ---------------------------------------------------------------------------
// GEMM1 machinery (R4-proven): CTA 128x128, kc=32, 2-buffer, 3-term split.
// Stage: Ah|Al|Bh|Bl each 2560 words (128 rows x PADW). 2 stages = 80 KB.
// ---------------------------------------------------------------------------
#define STG1 10240

__device__ __forceinline__ void g1_load(uint32_t sbase, int buf,
    const __nv_bfloat16* Ah, const __nv_bfloat16* Al,
    const __nv_bfloat16* Bh, const __nv_bfloat16* Bl,
    size_t kstride, int kc, int tid)
{
    const int r = tid >> 1;
    const int c0 = (tid & 1) * 2;
    const uint32_t so = sbase + (uint32_t)buf * (STG1 * 4);
    #pragma unroll
    for (int i = 0; i < 2; i++) {
        int c = c0 + i;
        uint32_t off = (uint32_t)(r * PADW + c * 4) * 4;
        size_t goff = (size_t)r * kstride + kc + c * 8;
        cp16(so + off,            Ah + goff);
        cp16(so + 2560 * 4 + off, Al + goff);
        cp16(so + 5120 * 4 + off, Bh + goff);
        cp16(so + 7680 * 4 + off, Bl + goff);
    }
}

__device__ __forceinline__ void g1_compute(const uint32_t* sm, int buf,
    float acc[4][4][4], int wm, int wn, int g, int tig)
{
    const uint32_t* Ahp = sm + buf * STG1;
    const uint32_t* Alp = Ahp + 2560;
    const uint32_t* Bhp = Ahp + 5120;
    const uint32_t* Blp = Ahp + 7680;
    #pragma unroll
    for (int ks = 0; ks < 2; ks++) {
        const int w = ks * 8 + tig;
        uint32_t ah[4][4], al[4][4];
        #pragma unroll
        for (int m = 0; m < 4; m++) {
            int r0 = wm * 64 + m * 16 + g, r1 = r0 + 8;
            ah[m][0] = Ahp[r0 * PADW + w];     ah[m][1] = Ahp[r1 * PADW + w];
            ah[m][2] = Ahp[r0 * PADW + w + 4]; ah[m][3] = Ahp[r1 * PADW + w + 4];
            al[m][0] = Alp[r0 * PADW + w];     al[m][1] = Alp[r1 * PADW + w];
            al[m][2] = Alp[r0 * PADW + w + 4]; al[m][3] = Alp[r1 * PADW + w + 4];
        }
        #pragma unroll
        for (int n = 0; n < 4; n++) {
            int nr = wn * 32 + n * 8 + g;
            uint32_t bh0 = Bhp[nr * PADW + w], bh1 = Bhp[nr * PADW + w + 4];
            uint32_t bl0 = Blp[nr * PADW + w], bl1 = Blp[nr * PADW + w + 4];
            #pragma unroll
            for (int m = 0; m < 4; m++) {
                mma_bf16(acc[m][n], ah[m][0], ah[m][1], ah[m][2], ah[m][3], bh0, bh1);
                mma_bf16(acc[m][n], ah[m][0], ah[m][1], ah[m][2], ah[m][3], bl0, bl1);
                mma_bf16(acc[m][n], al[m][0], al[m][1], al[m][2], al[m][3], bh0, bh1);
            }
        }
    }
}

// ---------------------------------------------------------------------------
// GEMM1: [A;..](1024x256) @ QT^T -> sim (mt<4) / E bf16-hi (mt>=4)
// grid (nt=512, mt=8), 256 threads. One sync per stage.
// ---------------------------------------------------------------------------
__global__ void __launch_bounds__(256) gemm1_mma() {
    extern __shared__ __align__(16) uint32_t sm[];
    const int nt = blockIdx.x;
    const int mt = blockIdx.y;
    const int tid = threadIdx.x;
    const int lane = tid & 31, wid = tid >> 5;
    const int wm = wid >> 2, wn = wid & 3;
    const int g = lane >> 2, tig = lane & 3;
    const uint32_t sbase = smem_u32(sm);

    const __nv_bfloat16* Ah = g_Ahi + (size_t)mt * 128 * Dd;
    const __nv_bfloat16* Al = g_Alo + (size_t)mt * 128 * Dd;
    const __nv_bfloat16* Bh = g_QThi + (size_t)nt * 128 * Dd;
    const __nv_bfloat16* Bl = g_QTlo + (size_t)nt * 128 * Dd;

    float acc[4][4][4] = {};
    const int NS = Dd / 32;   // 8

    g1_load(sbase, 0, Ah, Al, Bh, Bl, Dd, 0, tid);
    CPCOMMIT();
    for (int s = 0; s < NS; s++) {
        CPWAIT0();
        __syncthreads();
        if (s + 1 < NS) {
            g1_load(sbase, (s + 1) & 1, Ah, Al, Bh, Bl, Dd, (s + 1) * 32, tid);
            CPCOMMIT();
        }
        g1_compute(sm, s & 1, acc, wm, wn, g, tig);
    }

    // epilogue
    const int rbase = mt * 128 + wm * 64;
    const int col = nt * 128 + wn * 32;
    if (mt < 4) {
        #pragma unroll
        for (int m = 0; m < 4; m++) {
            int r0 = rbase + m * 16 + g;
            #pragma unroll
            for (int n = 0; n < 4; n++) {
                int c = col + n * 8 + tig * 2;
                *(float2*)&g_sim[(size_t)r0 * Kq + c] = make_float2(acc[m][n][0], acc[m][n][1]);
                *(float2*)&g_sim[(size_t)(r0 + 8) * Kq + c] = make_float2(acc[m][n][2], acc[m][n][3]);
            }
        }
    } else {
        #pragma unroll
        for (int m = 0; m < 4; m++) {
            int b0 = rbase - 512 + m * 16 + g;
            float s0 = 0.f, s1 = 0.f;
            #pragma unroll
            for (int n = 0; n < 4; n++) {
                int c = col + n * 8 + tig * 2;
                float e0 = __expf(acc[m][n][0] * (1.0f / T_DCf));
                float e1 = __expf(acc[m][n][1] * (1.0f / T_DCf));
                float e2 = __expf(acc[m][n][2] * (1.0f / T_DCf));
                float e3 = __expf(acc[m][n][3] * (1.0f / T_DCf));
                *(uint32_t*)&g_Ehi[(size_t)b0 * Kq + c] = pack_bf16(e0, e1);
                *(uint32_t*)&g_Ehi[(size_t)(b0 + 8) * Kq + c] = pack_bf16(e2, e3);
                s0 += e0 + e1;
                s1 += e2 + e3;
            }
            s0 += __shfl_xor_sync(0xffffffffu, s0, 1);
            s0 += __shfl_xor_sync(0xffffffffu, s0, 2);
            s1 += __shfl_xor_sync(0xffffffffu, s1, 1);
            s1 += __shfl_xor_sync(0xffffffffu, s1, 2);
            if (tig == 0) {
                g_psum[(size_t)b0 * 2048 + nt * 4 + wn] = s0;
                g_psum[(size_t)(b0 + 8) * 2048 + nt * 4 + wn] = s1;
            }
        }
    }
}

// ---------------------------------------------------------------------------
// GEMM2 machinery: 2-term (Eh x (Ph + Pl)). Stage: Ah|Bh|Bl = 7680 words
// = 30 KB; 2 stages = 60 KB -> 3 CTAs/SM.
// ---------------------------------------------------------------------------
#define STG2 7680

__device__ __forceinline__ void g2_load(uint32_t sbase, int buf,
    const __nv_bfloat16* Ah, const __nv_bfloat16* Bh, const __nv_bfloat16* Bl,
    int kc, int tid)
{
    const int r = tid >> 1;
    const int c0 = (tid & 1) * 2;
    const uint32_t so = sbase + (uint32_t)buf * (STG2 * 4);
    #pragma unroll
    for (int i = 0; i < 2; i++) {
        int c = c0 + i;
        uint32_t off = (uint32_t)(r * PADW + c * 4) * 4;
        size_t goff = (size_t)r * Kq + kc + c * 8;
        cp16(so + off,            Ah + goff);
        cp16(so + 2560 * 4 + off, Bh + goff);
        cp16(so + 5120 * 4 + off, Bl + goff);
    }
}

__device__ __forceinline__ void g2_compute(const uint32_t* sm, int buf,
    float acc[4][4][4], int wm, int wn, int g, int tig)
{
    const uint32_t* Ahp = sm + buf * STG2;
    const uint32_t* Bhp = Ahp + 2560;
    const uint32_t* Blp = Ahp + 5120;
    #pragma unroll
    for (int ks = 0; ks < 2; ks++) {
        const int w = ks * 8 + tig;
        uint32_t ah[4][4];
        #pragma unroll
        for (int m = 0; m < 4; m++) {
            int r0 = wm * 64 + m * 16 + g, r1 = r0 + 8;
            ah[m][0] = Ahp[r0 * PADW + w];     ah[m][1] = Ahp[r1 * PADW + w];
            ah[m][2] = Ahp[r0 * PADW + w + 4]; ah[m][3] = Ahp[r1 * PADW + w + 4];
        }
        #pragma unroll
        for (int n = 0; n < 4; n++) {
            int nr = wn * 32 + n * 8 + g;
            uint32_t bh0 = Bhp[nr * PADW + w], bh1 = Bhp[nr * PADW + w + 4];
            uint32_t bl0 = Blp[nr * PADW + w], bl1 = Blp[nr * PADW + w + 4];
            #pragma unroll
            for (int m = 0; m < 4; m++) {
                mma_bf16(acc[m][n], ah[m][0], ah[m][1], ah[m][2], ah[m][3], bh0, bh1);
                mma_bf16(acc[m][n], ah[m][0], ah[m][1], ah[m][2], ah[m][3], bl0, bl1);
            }
        }
    }
}

// ---------------------------------------------------------------------------
// GEMM2 (split-K): part[sp] = Eh(512x65536) @ (Ph+Pl)^T
// grid (nt=8, mt=4, sp=8), 256 threads. One sync per stage.
// ---------------------------------------------------------------------------
__global__ void __launch_bounds__(256) gemm2_mma() {
    extern __shared__ __align__(16) uint32_t sm[];
    const int nt = blockIdx.x;
    const int mt = blockIdx.y;
    const int sp = blockIdx.z;
    const int tid = threadIdx.x;
    const int lane = tid & 31, wid = tid >> 5;
    const int wm = wid >> 2, wn = wid & 3;
    const int g = lane >> 2, tig = lane & 3;
    const uint32_t sbase = smem_u32(sm);

    const size_t k0 = (size_t)sp * (Kq / SPLIT);
    const __nv_bfloat16* Ah = g_Ehi + (size_t)mt * 128 * Kq + k0;
    const __nv_bfloat16* Bh = g_Phi + (size_t)nt * 128 * Kq + k0;
    const __nv_bfloat16* Bl = g_Plo + (size_t)nt * 128 * Kq + k0;

    float acc[4][4][4] = {};
    const int NS = (Kq / SPLIT) / 32;   // 256

    g2_load(sbase, 0, Ah, Bh, Bl, 0, tid);
    CPCOMMIT();
    for (int s = 0; s < NS; s++) {
        CPWAIT0();
        __syncthreads();
        if (s + 1 < NS) {
            g2_load(sbase, (s + 1) & 1, Ah, Bh, Bl, (s + 1) * 32, tid);
            CPCOMMIT();
        }
        g2_compute(sm, s & 1, acc, wm, wn, g, tig);
    }

    // epilogue: split-K partials
    #pragma unroll
    for (int m = 0; m < 4; m++) {
        int b = mt * 128 + wm * 64 + m * 16 + g;
        #pragma unroll
        for (int n = 0; n < 4; n++) {
            int c = nt * 128 + wn * 32 + n * 8 + tig * 2;
            *(float2*)&g_part[((size_t)sp * 512 + b) * Cpad + c] =
                make_float2(acc[m][n][0], acc[m][n][1]);
            *(float2*)&g_part[((size_t)sp * 512 + b + 8) * Cpad + c] =
                make_float2(acc[m][n][2], acc[m][n][3]);
        }
    }
}

// ---------------------------------------------------------------------------
// invz / supcon / fcdc / finalize (unchanged)
// ---------------------------------------------------------------------------
__global__ void __launch_bounds__(256) invz_kernel() {
    const int b = blockIdx.x;
    const int tid = threadIdx.x;
    float s = 0.f;
    for (int i = tid; i < 2048; i += 256) s += g_psum[(size_t)b * 2048 + i];
    __shared__ float red[256];
    red[tid] = s;
    __syncthreads();
    for (int o = 128; o > 0; o >>= 1) {
        if (tid < o) red[tid] += red[tid + o];
        __syncthreads();
    }
    if (tid == 0) g_invZ[b] = 1.0f / red[0];
}

#define MAXTIES 2048
__global__ void __launch_bounds__(256) supcon_kernel(
    const void* __restrict__ qlabel,
    const void* __restrict__ target,
    const int*  __restrict__ knnk)
{
    const int b = blockIdx.x;
    const float* row = g_sim + (size_t)b * Kq;
    const int tid = threadIdx.x;
    const int NT = 256;
    const int kneed = knnk[0];

    __shared__ unsigned hist[256];
    __shared__ unsigned s_prefix, s_desired;
    __shared__ int s_ties;
    __shared__ int tie_idx[MAXTIES];
    __shared__ float ra[256], rp[256];

    if (tid == 0) { s_prefix = 0; s_desired = (unsigned)kneed; }
    __syncthreads();

    for (int pass = 0; pass < 4; pass++) {
        const int shift = 24 - pass * 8;
        for (int i = tid; i < 256; i += NT) hist[i] = 0;
        __syncthreads();
        const unsigned pref = s_prefix;
        for (int k = tid; k < Kq; k += NT) {
            unsigned u = fmap(row[k]);
            bool ok = (pass == 0) || ((u >> (shift + 8)) == pref);
            if (ok) atomicAdd(&hist[(u >> shift) & 255u], 1u);
        }
        __syncthreads();
        if (tid == 0) {
            unsigned des = s_desired;
            for (int bin = 255; bin >= 0; bin--) {
                unsigned c = hist[bin];
                if (c >= des) {
                    s_prefix = (pref << 8) | (unsigned)bin;
                    s_desired = des;
                    break;
                }
                des -= c;
            }
        }
        __syncthreads();
    }

    const unsigned u200 = s_prefix;
    const unsigned des = s_desired;
    if (tid == 0) s_ties = 0;
    __syncthreads();

    float sa = 0.f, sp = 0.f;
    const long long tgt = load_label(target, b);
    for (int k = tid; k < Kq; k += NT) {
        float sv = row[k];
        unsigned u = fmap(sv);
        if (u > u200) {
            float e = __expf(sv * (1.0f / T_SUPf));
            sa += e;
            if (load_label(qlabel, k) == tgt) sp += e;
        } else if (u == u200) {
            int p = atomicAdd(&s_ties, 1);
            if (p < MAXTIES) tie_idx[p] = k;
        }
    }
    ra[tid] = sa; rp[tid] = sp;
    __syncthreads();
    for (int o = 128; o > 0; o >>= 1) {
        if (tid < o) { ra[tid] += ra[tid + o]; rp[tid] += rp[tid + o]; }
        __syncthreads();
    }

    if (tid == 0) {
        float SA = ra[0], SP = rp[0];
        int t = min(s_ties, MAXTIES);
        for (int i = 1; i < t; i++) {
            int v = tie_idx[i]; int j = i - 1;
            while (j >= 0 && tie_idx[j] > v) { tie_idx[j + 1] = tie_idx[j]; j--; }
            tie_idx[j + 1] = v;
        }
        int take = min((int)des, t);
        for (int i = 0; i < take; i++) {
            int k = tie_idx[i];
            float e = __expf(row[k] * (1.0f / T_SUPf));
            SA += e;
            if (load_label(qlabel, k) == tgt) SP += e;
        }
        float gt = SP / SA;
        g_row_supin[b] = (gt > EPSf) ? (-__logf(gt)) : 0.0f;
    }
}

__global__ void __launch_bounds__(256) fcdc_kernel(
    const float* __restrict__ qlog,
    const void* __restrict__ target)
{
    const int b = blockIdx.x;
    const int tid = threadIdx.x;
    const float* q = qlog + (size_t)b * Cc;
    __shared__ float red[256];

    float mx = -3.4e38f;
    for (int c = tid; c < Cc; c += 256) mx = fmaxf(mx, q[c]);
    red[tid] = mx; __syncthreads();
    for (int o = 128; o > 0; o >>= 1) { if (tid < o) red[tid] = fmaxf(red[tid], red[tid + o]); __syncthreads(); }
    const float Mx = red[0]; __syncthreads();

    float mn = 3.4e38f;
    for (int c = tid; c < Cc; c += 256) mn = fminf(mn, q[c]);
    red[tid] = mn; __syncthreads();
    for (int o = 128; o > 0; o >>= 1) { if (tid < o) red[tid] = fminf(red[tid], red[tid + o]); __syncthreads(); }
    const float Mn = red[0]; __syncthreads();

    float se = 0.f;
    for (int c = tid; c < Cc; c += 256) se += __expf(q[c] - Mx);
    red[tid] = se; __syncthreads();
    for (int o = 128; o > 0; o >>= 1) { if (tid < o) red[tid] += red[tid + o]; __syncthreads(); }
    const float SE = red[0]; __syncthreads();

    const float logZ = __logf(SE);
    const bool qmask = (__expf(Mn - Mx) / SE) > EPSf;
    const float invZk = g_invZ[b];
    const long long t = load_label(target, b);

    float fcs = 0.f, kl = 0.f;
    for (int c = tid; c < Cc; c += 256) {
        float lq = q[c] - Mx - logZ;
        float oh = (c == (int)t) ? (1.0f - LSm) : (LSm / (float)(Cc - 1));
        fcs += oh * lq;
        float ps = 0.f;
        #pragma unroll
        for (int s = 0; s < SPLIT; s++)
            ps += g_part[((size_t)s * 512 + b) * Cpad + c];
        float dct = invZk * ps;
        if (dct > 0.f) kl += dct * (__logf(dct) - lq);
    }
    red[tid] = fcs; __syncthreads();
    for (int o = 128; o > 0; o >>= 1) { if (tid < o) red[tid] += red[tid + o]; __syncthreads(); }
    const float FCS = red[0]; __syncthreads();
    red[tid] = kl; __syncthreads();
    for (int o = 128; o > 0; o >>= 1) { if (tid < o) red[tid] += red[tid + o]; __syncthreads(); }
    if (tid == 0) {
        g_row_fc[b] = qmask ? FCS : 0.f;
        g_row_dc[b] = qmask ? red[0] : 0.f;
    }
}

__global__ void __launch_bounds__(512) finalize_kernel(float* __restrict__ out) {
    const int tid = threadIdx.x;
    __shared__ float r[512];

    r[tid] = g_row_supin[tid]; __syncthreads();
    for (int o = 256; o > 0; o >>= 1) { if (tid < o) r[tid] += r[tid + o]; __syncthreads(); }
    if (tid == 0) out[0] = r[0] / (float)Bsz;
    __syncthreads();

    r[tid] = g_row_fc[tid]; __syncthreads();
    for (int o = 256; o > 0; o >>= 1) { if (tid < o) r[tid] += r[tid + o]; __syncthreads(); }
    if (tid == 0) out[1] = -r[0] / (float)Bsz;
    __syncthreads();

    r[tid] = g_row_dc[tid]; __syncthreads();
    for (int o = 256; o > 0; o >>= 1) { if (tid < o) r[tid] += r[tid + o]; __syncthreads(); }
    if (tid == 0) out[2] = r[0] / (float)Bsz;
}

// ---------------------------------------------------------------------------
extern "C" void kernel_launch(void* const* d_in, const int* in_sizes, int n_in,
                              void* d_out, int out_size)
{
    const float* normq  = (const float*)d_in[0];
    const float* qlog   = (const float*)d_in[1];
    const float* kfeat  = (const float*)d_in[2];
    // d_in[3] = logits_k (unused)
    const float* queue  = (const float*)d_in[4];
    const float* qlp    = (const float*)d_in[5];
    const void*  qlabel = d_in[6];
    const void*  target = d_in[7];
    const int*   knnk   = (const int*)d_in[8];
    float* out = (float*)d_out;

    const int SMEM1 = 2 * STG1 * 4;  // 80 KB
    const int SMEM2 = 2 * STG2 * 4;  // 60 KB
    cudaFuncSetAttribute(gemm1_mma, cudaFuncAttributeMaxDynamicSharedMemorySize, SMEM1);
    cudaFuncSetAttribute(gemm2_mma, cudaFuncAttributeMaxDynamicSharedMemorySize, SMEM2);

    // order chosen so gemm2_mma is the 4th launch (the one ncu captures)
    convAQ_kernel<<<8448, 256>>>(normq, kfeat, queue);
    convP_kernel<<<dim3(32, 1024), 256>>>(qlp);
    gemm1_mma<<<dim3(512, 8), 256, SMEM1>>>();
    gemm2_mma<<<dim3(8, 4, 8), 256, SMEM2>>>();
    detect_kernel<<<1, 32>>>((const int*)qlabel);
    supcon_kernel<<<512, 256>>>(qlabel, target, knnk);
    invz_kernel<<<512, 256>>>();
    fcdc_kernel<<<512, 256>>>(qlog, target);
    finalize_kernel<<<1, 512>>>(out);
    (void)in_sizes; (void)n_in; (void)out_size;
}

// round 7
// speedup vs baseline: 1.6865x; 1.2054x over previous
#include <cuda_runtime.h>
#include <cuda_bf16.h>
#include <cstdint>

// Problem constants
#define Bsz 512
#define Dd  256
#define Kq  65536
#define Cc  1000
#define Cpad 1024
#define T_SUPf 0.07f
#define T_DCf  0.1f
#define LSm  0.1f
#define EPSf 1e-8f
#define SPLIT2 16
#define PADW 20   // gemm1: 16 data words + 4 pad
#define PADW2 36  // gemm2: 32 data words + 4 pad (stride 36 = 4 mod 32, conflict-free)

// -------- scratch (static device globals) ----------
__device__ float g_sim[(size_t)512 * Kq];
__device__ __align__(16) __nv_bfloat16 g_Ehi[(size_t)512 * Kq];
__device__ __align__(16) __nv_bfloat16 g_Ahi[(size_t)1024 * Dd];
__device__ __align__(16) __nv_bfloat16 g_Alo[(size_t)1024 * Dd];
__device__ __align__(16) __nv_bfloat16 g_QThi[(size_t)Kq * Dd];
__device__ __align__(16) __nv_bfloat16 g_QTlo[(size_t)Kq * Dd];
__device__ __align__(16) __nv_bfloat16 g_Phi[(size_t)Cpad * Kq];
__device__ float g_psum[(size_t)512 * 2048];
__device__ float g_part[(size_t)SPLIT2 * 512 * Cpad];
__device__ float g_invZ[512];
__device__ float g_row_supin[512];
__device__ float g_row_fc[512];
__device__ float g_row_dc[512];
__device__ int   g_is64;

// ---------------- helpers ----------------
__device__ __forceinline__ uint32_t smem_u32(const void* p) {
    uint32_t a;
    asm("{ .reg .u64 t; cvta.to.shared.u64 t, %1; cvt.u32.u64 %0, t; }" : "=r"(a) : "l"(p));
    return a;
}
__device__ __forceinline__ void cp16(uint32_t dst, const void* src) {
    asm volatile("cp.async.cg.shared.global [%0], [%1], 16;\n" :: "r"(dst), "l"(src));
}
#define CPCOMMIT() asm volatile("cp.async.commit_group;\n" ::: "memory")
#define CPWAIT0()  asm volatile("cp.async.wait_group 0;\n" ::: "memory")

__device__ __forceinline__ void mma_bf16(float* c, uint32_t a0, uint32_t a1,
                                         uint32_t a2, uint32_t a3,
                                         uint32_t b0, uint32_t b1) {
    asm volatile(
        "mma.sync.aligned.m16n8k16.row.col.f32.bf16.bf16.f32 "
        "{%0,%1,%2,%3}, {%4,%5,%6,%7}, {%8,%9}, {%0,%1,%2,%3};\n"
        : "+f"(c[0]), "+f"(c[1]), "+f"(c[2]), "+f"(c[3])
        : "r"(a0), "r"(a1), "r"(a2), "r"(a3), "r"(b0), "r"(b1));
}

__device__ __forceinline__ void split2(float f0, float f1, uint32_t& hi, uint32_t& lo) {
    __nv_bfloat16 h0 = __float2bfloat16(f0), h1 = __float2bfloat16(f1);
    float r0 = f0 - __bfloat162float(h0);
    float r1 = f1 - __bfloat162float(h1);
    __nv_bfloat16 l0 = __float2bfloat16(r0), l1 = __float2bfloat16(r1);
    hi = ((uint32_t)__bfloat16_as_ushort(h1) << 16) | (uint32_t)__bfloat16_as_ushort(h0);
    lo = ((uint32_t)__bfloat16_as_ushort(l1) << 16) | (uint32_t)__bfloat16_as_ushort(l0);
}
__device__ __forceinline__ uint32_t pack_bf16(float f0, float f1) {
    return ((uint32_t)__bfloat16_as_ushort(__float2bfloat16(f1)) << 16)
         | (uint32_t)__bfloat16_as_ushort(__float2bfloat16(f0));
}

__device__ __forceinline__ unsigned fmap(float f) {
    unsigned u = __float_as_uint(f);
    return (u & 0x80000000u) ? ~u : (u | 0x80000000u);
}

// ---------------------------------------------------------------------------
__global__ void detect_kernel(const int* __restrict__ qlabel_raw) {
    if (threadIdx.x == 0 && blockIdx.x == 0) {
        int is64 = 1;
        for (int i = 0; i < 4096; i++) {
            if (qlabel_raw[2 * i + 1] != 0) { is64 = 0; break; }
        }
        g_is64 = is64;
    }
}
__device__ __forceinline__ long long load_label(const void* p, int i) {
    if (g_is64) return ((const long long*)p)[i];
    return (long long)((const int*)p)[i];
}

// ---------------------------------------------------------------------------
// convAQ: fused convA + convQ (unchanged).
// ---------------------------------------------------------------------------
__global__ void __launch_bounds__(256) convAQ_kernel(
    const float* __restrict__ nq, const float* __restrict__ kf,
    const float* __restrict__ Q)
{
    const int t = threadIdx.x;
    if (blockIdx.x < 8192) {
        __shared__ float s[32][65];
        const int n0 = (blockIdx.x & 2047) * 32, d0 = (blockIdx.x >> 11) * 64;
        const int nl = t & 31, dl = t >> 5;
        #pragma unroll
        for (int i = 0; i < 8; i++) {
            int d = i * 8 + dl;
            s[nl][d] = Q[(size_t)(d0 + d) * Kq + n0 + nl];
        }
        __syncthreads();
        const int n = t >> 3, dq = (t & 7) * 8;
        uint32_t hi[4], lo[4];
        #pragma unroll
        for (int j = 0; j < 4; j++)
            split2(s[n][dq + 2 * j], s[n][dq + 2 * j + 1], hi[j], lo[j]);
        size_t off = (size_t)(n0 + n) * Dd + d0 + dq;
        *(uint4*)(g_QThi + off) = make_uint4(hi[0], hi[1], hi[2], hi[3]);
        *(uint4*)(g_QTlo + off) = make_uint4(lo[0], lo[1], lo[2], lo[3]);
    } else {
        size_t i = ((size_t)(blockIdx.x - 8192) * 256 + t) * 4;
        const size_t half = (size_t)512 * Dd;
        const float* src = (i < half) ? (nq + i) : (kf + (i - half));
        float4 v = *(const float4*)src;
        uint32_t h0, l0, h1, l1;
        split2(v.x, v.y, h0, l0);
        split2(v.z, v.w, h1, l1);
        *(uint2*)(g_Ahi + i) = make_uint2(h0, h1);
        *(uint2*)(g_Alo + i) = make_uint2(l0, l1);
    }
}

// ---------------------------------------------------------------------------
// convP: P [1000][65536] fp32 -> Phi only (rows >= 1000 zero)
// ---------------------------------------------------------------------------
__global__ void __launch_bounds__(256) convP_kernel(const float* __restrict__ P) {
    const int c = blockIdx.y;
    const size_t k = (size_t)blockIdx.x * 2048 + threadIdx.x * 8;
    size_t off = (size_t)c * Kq + k;
    uint32_t hi[4];
    if (c < Cc) {
        float4 v0 = *(const float4*)(P + off);
        float4 v1 = *(const float4*)(P + off + 4);
        hi[0] = pack_bf16(v0.x, v0.y);
        hi[1] = pack_bf16(v0.z, v0.w);
        hi[2] = pack_bf16(v1.x, v1.y);
        hi[3] = pack_bf16(v1.z, v1.w);
    } else {
        hi[0] = hi[1] = hi[2] = hi[3] = 0u;
    }
    *(uint4*)(g_Phi + off) = make_uint4(hi[0], hi[1], hi[2], hi[3]);
}

// ---------------------------------------------------------------------------
// GEMM1 (unchanged, R4/R6-proven): CTA 128x128, kc=32, 2-buffer, 3-term.
// ---------------------------------------------------------------------------
#define STG1 10240

__device__ __forceinline__ void g1_load(uint32_t sbase, int buf,
    const __nv_bfloat16* Ah, const __nv_bfloat16* Al,
    const __nv_bfloat16* Bh, const __nv_bfloat16* Bl,
    size_t kstride, int kc, int tid)
{
    const int r = tid >> 1;
    const int c0 = (tid & 1) * 2;
    const uint32_t so = sbase + (uint32_t)buf * (STG1 * 4);
    #pragma unroll
    for (int i = 0; i < 2; i++) {
        int c = c0 + i;
        uint32_t off = (uint32_t)(r * PADW + c * 4) * 4;
        size_t goff = (size_t)r * kstride + kc + c * 8;
        cp16(so + off,            Ah + goff);
        cp16(so + 2560 * 4 + off, Al + goff);
        cp16(so + 5120 * 4 + off, Bh + goff);
        cp16(so + 7680 * 4 + off, Bl + goff);
    }
}

__device__ __forceinline__ void g1_compute(const uint32_t* sm, int buf,
    float acc[4][4][4], int wm, int wn, int g, int tig)
{
    const uint32_t* Ahp = sm + buf * STG1;
    const uint32_t* Alp = Ahp + 2560;
    const uint32_t* Bhp = Ahp + 5120;
    const uint32_t* Blp = Ahp + 7680;
    #pragma unroll
    for (int ks = 0; ks < 2; ks++) {
        const int w = ks * 8 + tig;
        uint32_t ah[4][4], al[4][4];
        #pragma unroll
        for (int m = 0; m < 4; m++) {
            int r0 = wm * 64 + m * 16 + g, r1 = r0 + 8;
            ah[m][0] = Ahp[r0 * PADW + w];     ah[m][1] = Ahp[r1 * PADW + w];
            ah[m][2] = Ahp[r0 * PADW + w + 4]; ah[m][3] = Ahp[r1 * PADW + w + 4];
            al[m][0] = Alp[r0 * PADW + w];     al[m][1] = Alp[r1 * PADW + w];
            al[m][2] = Alp[r0 * PADW + w + 4]; al[m][3] = Alp[r1 * PADW + w + 4];
        }
        #pragma unroll
        for (int n = 0; n < 4; n++) {
            int nr = wn * 32 + n * 8 + g;
            uint32_t bh0 = Bhp[nr * PADW + w], bh1 = Bhp[nr * PADW + w + 4];
            uint32_t bl0 = Blp[nr * PADW + w], bl1 = Blp[nr * PADW + w + 4];
            #pragma unroll
            for (int m = 0; m < 4; m++) {
                mma_bf16(acc[m][n], ah[m][0], ah[m][1], ah[m][2], ah[m][3], bh0, bh1);
                mma_bf16(acc[m][n], ah[m][0], ah[m][1], ah[m][2], ah[m][3], bl0, bl1);
                mma_bf16(acc[m][n], al[m][0], al[m][1], al[m][2], al[m][3], bh0, bh1);
            }
        }
    }
}

__global__ void __launch_bounds__(256) gemm1_mma() {
    extern __shared__ __align__(16) uint32_t sm[];
    const int nt = blockIdx.x;
    const int mt = blockIdx.y;
    const int tid = threadIdx.x;
    const int lane = tid & 31, wid = tid >> 5;
    const int wm = wid >> 2, wn = wid & 3;
    const int g = lane >> 2, tig = lane & 3;
    const uint32_t sbase = smem_u32(sm);

    const __nv_bfloat16* Ah = g_Ahi + (size_t)mt * 128 * Dd;
    const __nv_bfloat16* Al = g_Alo + (size_t)mt * 128 * Dd;
    const __nv_bfloat16* Bh = g_QThi + (size_t)nt * 128 * Dd;
    const __nv_bfloat16* Bl = g_QTlo + (size_t)nt * 128 * Dd;

    float acc[4][4][4] = {};
    const int NS = Dd / 32;   // 8

    g1_load(sbase, 0, Ah, Al, Bh, Bl, Dd, 0, tid);
    CPCOMMIT();
    for (int s = 0; s < NS; s++) {
        CPWAIT0();
        __syncthreads();
        if (s + 1 < NS) {
            g1_load(sbase, (s + 1) & 1, Ah, Al, Bh, Bl, Dd, (s + 1) * 32, tid);
            CPCOMMIT();
        }
        g1_compute(sm, s & 1, acc, wm, wn, g, tig);
    }

    const int rbase = mt * 128 + wm * 64;
    const int col = nt * 128 + wn * 32;
    if (mt < 4) {
        #pragma unroll
        for (int m = 0; m < 4; m++) {
            int r0 = rbase + m * 16 + g;
            #pragma unroll
            for (int n = 0; n < 4; n++) {
                int c = col + n * 8 + tig * 2;
                *(float2*)&g_sim[(size_t)r0 * Kq + c] = make_float2(acc[m][n][0], acc[m][n][1]);
                *(float2*)&g_sim[(size_t)(r0 + 8) * Kq + c] = make_float2(acc[m][n][2], acc[m][n][3]);
            }
        }
    } else {
        #pragma unroll
        for (int m = 0; m < 4; m++) {
            int b0 = rbase - 512 + m * 16 + g;
            float s0 = 0.f, s1 = 0.f;
            #pragma unroll
            for (int n = 0; n < 4; n++) {
                int c = col + n * 8 + tig * 2;
                float e0 = __expf(acc[m][n][0] * (1.0f / T_DCf));
                float e1 = __expf(acc[m][n][1] * (1.0f / T_DCf));
                float e2 = __expf(acc[m][n][2] * (1.0f / T_DCf));
                float e3 = __expf(acc[m][n][3] * (1.0f / T_DCf));
                *(uint32_t*)&g_Ehi[(size_t)b0 * Kq + c] = pack_bf16(e0, e1);
                *(uint32_t*)&g_Ehi[(size_t)(b0 + 8) * Kq + c] = pack_bf16(e2, e3);
                s0 += e0 + e1;
                s1 += e2 + e3;
            }
            s0 += __shfl_xor_sync(0xffffffffu, s0, 1);
            s0 += __shfl_xor_sync(0xffffffffu, s0, 2);
            s1 += __shfl_xor_sync(0xffffffffu, s1, 1);
            s1 += __shfl_xor_sync(0xffffffffu, s1, 2);
            if (tig == 0) {
                g_psum[(size_t)b0 * 2048 + nt * 4 + wn] = s0;
                g_psum[(size_t)(b0 + 8) * 2048 + nt * 4 + wn] = s1;
            }
        }
    }
}

// ---------------------------------------------------------------------------
// GEMM2 v3: 1-term Eh x Ph. CTA 128x128, kc=64, 2-stage, SPLIT2=16.
// Stage: A 128xPADW2 + B 128xPADW2 words = 9216 w = 36 KB; 2 stages = 72 KB.
// grid (nt=8, mt=4, sp=16) = 512 CTAs, NS = 64 stages.
// ---------------------------------------------------------------------------
#define STG2 (128 * PADW2 * 2)       // 9216 words per stage
#define ABLK (128 * PADW2 * 4)       // byte offset of B block within stage

__device__ __forceinline__ void g2_load(uint32_t sbase, int buf,
    const __nv_bfloat16* Ah, const __nv_bfloat16* Bh, int kc, int tid)
{
    const int r = tid >> 1;
    const int c0 = (tid & 1) * 4;
    const uint32_t so = sbase + (uint32_t)buf * (STG2 * 4);
    #pragma unroll
    for (int i = 0; i < 4; i++) {
        int c = c0 + i;
        uint32_t off = (uint32_t)(r * PADW2 + c * 4) * 4;
        size_t goff = (size_t)r * Kq + kc + c * 8;
        cp16(so + off,        Ah + goff);
        cp16(so + ABLK + off, Bh + goff);
    }
}

__device__ __forceinline__ void g2_compute(const uint32_t* sm, int buf,
    float acc[4][4][4], int wm, int wn, int g, int tig)
{
    const uint32_t* Ap = sm + buf * STG2;
    const uint32_t* Bp = Ap + 128 * PADW2;
    #pragma unroll
    for (int ks = 0; ks < 4; ks++) {
        const int w = ks * 8 + tig;
        uint32_t ah[4][4];
        #pragma unroll
        for (int m = 0; m < 4; m++) {
            int r0 = wm * 64 + m * 16 + g, r1 = r0 + 8;
            ah[m][0] = Ap[r0 * PADW2 + w];     ah[m][1] = Ap[r1 * PADW2 + w];
            ah[m][2] = Ap[r0 * PADW2 + w + 4]; ah[m][3] = Ap[r1 * PADW2 + w + 4];
        }
        #pragma unroll
        for (int n = 0; n < 4; n++) {
            int nr = wn * 32 + n * 8 + g;
            uint32_t b0 = Bp[nr * PADW2 + w], b1 = Bp[nr * PADW2 + w + 4];
            #pragma unroll
            for (int m = 0; m < 4; m++)
                mma_bf16(acc[m][n], ah[m][0], ah[m][1], ah[m][2], ah[m][3], b0, b1);
        }
    }
}

__global__ void __launch_bounds__(256) gemm2_mma() {
    extern __shared__ __align__(16) uint32_t sm[];
    const int nt = blockIdx.x;   // 0..7
    const int mt = blockIdx.y;   // 0..3
    const int sp = blockIdx.z;   // 0..15
    const int tid = threadIdx.x;
    const int lane = tid & 31, wid = tid >> 5;
    const int wm = wid >> 2, wn = wid & 3;
    const int g = lane >> 2, tig = lane & 3;
    const uint32_t sbase = smem_u32(sm);

    const size_t k0 = (size_t)sp * (Kq / SPLIT2);
    const __nv_bfloat16* Ah = g_Ehi + (size_t)mt * 128 * Kq + k0;
    const __nv_bfloat16* Bh = g_Phi + (size_t)nt * 128 * Kq + k0;

    float acc[4][4][4] = {};
    const int NS = (Kq / SPLIT2) / 64;   // 64

    g2_load(sbase, 0, Ah, Bh, 0, tid);
    CPCOMMIT();
    for (int s = 0; s < NS; s++) {
        CPWAIT0();
        __syncthreads();
        if (s + 1 < NS) {
            g2_load(sbase, (s + 1) & 1, Ah, Bh, (s + 1) * 64, tid);
            CPCOMMIT();
        }
        g2_compute(sm, s & 1, acc, wm, wn, g, tig);
    }

    #pragma unroll
    for (int m = 0; m < 4; m++) {
        int b = mt * 128 + wm * 64 + m * 16 + g;
        #pragma unroll
        for (int n = 0; n < 4; n++) {
            int c = nt * 128 + wn * 32 + n * 8 + tig * 2;
            *(float2*)&g_part[((size_t)sp * 512 + b) * Cpad + c] =
                make_float2(acc[m][n][0], acc[m][n][1]);
            *(float2*)&g_part[((size_t)sp * 512 + b + 8) * Cpad + c] =
                make_float2(acc[m][n][2], acc[m][n][3]);
        }
    }
}

// ---------------------------------------------------------------------------
// invz / supcon / fcdc / finalize
// ---------------------------------------------------------------------------
__global__ void __launch_bounds__(256) invz_kernel() {
    const int b = blockIdx.x;
    const int tid = threadIdx.x;
    float s = 0.f;
    for (int i = tid; i < 2048; i += 256) s += g_psum[(size_t)b * 2048 + i];
    __shared__ float red[256];
    red[tid] = s;
    __syncthreads();
    for (int o = 128; o > 0; o >>= 1) {
        if (tid < o) red[tid] += red[tid + o];
        __syncthreads();
    }
    if (tid == 0) g_invZ[b] = 1.0f / red[0];
}

#define MAXTIES 2048
__global__ void __launch_bounds__(256) supcon_kernel(
    const void* __restrict__ qlabel,
    const void* __restrict__ target,
    const int*  __restrict__ knnk)
{
    const int b = blockIdx.x;
    const float* row = g_sim + (size_t)b * Kq;
    const int tid = threadIdx.x;
    const int NT = 256;
    const int kneed = knnk[0];

    __shared__ unsigned hist[256];
    __shared__ unsigned s_prefix, s_desired;
    __shared__ int s_ties;
    __shared__ int tie_idx[MAXTIES];
    __shared__ float ra[256], rp[256];

    if (tid == 0) { s_prefix = 0; s_desired = (unsigned)kneed; }
    __syncthreads();

    for (int pass = 0; pass < 4; pass++) {
        const int shift = 24 - pass * 8;
        for (int i = tid; i < 256; i += NT) hist[i] = 0;
        __syncthreads();
        const unsigned pref = s_prefix;
        for (int k = tid; k < Kq; k += NT) {
            unsigned u = fmap(row[k]);
            bool ok = (pass == 0) || ((u >> (shift + 8)) == pref);
            if (ok) atomicAdd(&hist[(u >> shift) & 255u], 1u);
        }
        __syncthreads();
        if (tid == 0) {
            unsigned des = s_desired;
            for (int bin = 255; bin >= 0; bin--) {
                unsigned c = hist[bin];
                if (c >= des) {
                    s_prefix = (pref << 8) | (unsigned)bin;
                    s_desired = des;
                    break;
                }
                des -= c;
            }
        }
        __syncthreads();
    }

    const unsigned u200 = s_prefix;
    const unsigned des = s_desired;
    if (tid == 0) s_ties = 0;
    __syncthreads();

    float sa = 0.f, sp = 0.f;
    const long long tgt = load_label(target, b);
    for (int k = tid; k < Kq; k += NT) {
        float sv = row[k];
        unsigned u = fmap(sv);
        if (u > u200) {
            float e = __expf(sv * (1.0f / T_SUPf));
            sa += e;
            if (load_label(qlabel, k) == tgt) sp += e;
        } else if (u == u200) {
            int p = atomicAdd(&s_ties, 1);
            if (p < MAXTIES) tie_idx[p] = k;
        }
    }
    ra[tid] = sa; rp[tid] = sp;
    __syncthreads();
    for (int o = 128; o > 0; o >>= 1) {
        if (tid < o) { ra[tid] += ra[tid + o]; rp[tid] += rp[tid + o]; }
        __syncthreads();
    }

    if (tid == 0) {
        float SA = ra[0], SP = rp[0];
        int t = min(s_ties, MAXTIES);
        for (int i = 1; i < t; i++) {
            int v = tie_idx[i]; int j = i - 1;
            while (j >= 0 && tie_idx[j] > v) { tie_idx[j + 1] = tie_idx[j]; j--; }
            tie_idx[j + 1] = v;
        }
        int take = min((int)des, t);
        for (int i = 0; i < take; i++) {
            int k = tie_idx[i];
            float e = __expf(row[k] * (1.0f / T_SUPf));
            SA += e;
            if (load_label(qlabel, k) == tgt) SP += e;
        }
        float gt = SP / SA;
        g_row_supin[b] = (gt > EPSf) ? (-__logf(gt)) : 0.0f;
    }
}

__global__ void __launch_bounds__(256) fcdc_kernel(
    const float* __restrict__ qlog,
    const void* __restrict__ target)
{
    const int b = blockIdx.x;
    const int tid = threadIdx.x;
    const float* q = qlog + (size_t)b * Cc;
    __shared__ float red[256];

    float mx = -3.4e38f;
    for (int c = tid; c < Cc; c += 256) mx = fmaxf(mx, q[c]);
    red[tid] = mx; __syncthreads();
    for (int o = 128; o > 0; o >>= 1) { if (tid < o) red[tid] = fmaxf(red[tid], red[tid + o]); __syncthreads(); }
    const float Mx = red[0]; __syncthreads();

    float mn = 3.4e38f;
    for (int c = tid; c < Cc; c += 256) mn = fminf(mn, q[c]);
    red[tid] = mn; __syncthreads();
    for (int o = 128; o > 0; o >>= 1) { if (tid < o) red[tid] = fminf(red[tid], red[tid + o]); __syncthreads(); }
    const float Mn = red[0]; __syncthreads();

    float se = 0.f;
    for (int c = tid; c < Cc; c += 256) se += __expf(q[c] - Mx);
    red[tid] = se; __syncthreads();
    for (int o = 128; o > 0; o >>= 1) { if (tid < o) red[tid] += red[tid + o]; __syncthreads(); }
    const float SE = red[0]; __syncthreads();

    const float logZ = __logf(SE);
    const bool qmask = (__expf(Mn - Mx) / SE) > EPSf;
    const float invZk = g_invZ[b];
    const long long t = load_label(target, b);

    float fcs = 0.f, kl = 0.f;
    for (int c = tid; c < Cc; c += 256) {
        float lq = q[c] - Mx - logZ;
        float oh = (c == (int)t) ? (1.0f - LSm) : (LSm / (float)(Cc - 1));
        fcs += oh * lq;
        float ps = 0.f;
        #pragma unroll
        for (int s = 0; s < SPLIT2; s++)
            ps += g_part[((size_t)s * 512 + b) * Cpad + c];
        float dct = invZk * ps;
        if (dct > 0.f) kl += dct * (__logf(dct) - lq);
    }
    red[tid] = fcs; __syncthreads();
    for (int o = 128; o > 0; o >>= 1) { if (tid < o) red[tid] += red[tid + o]; __syncthreads(); }
    const float FCS = red[0]; __syncthreads();
    red[tid] = kl; __syncthreads();
    for (int o = 128; o > 0; o >>= 1) { if (tid < o) red[tid] += red[tid + o]; __syncthreads(); }
    if (tid == 0) {
        g_row_fc[b] = qmask ? FCS : 0.f;
        g_row_dc[b] = qmask ? red[0] : 0.f;
    }
}

__global__ void __launch_bounds__(512) finalize_kernel(float* __restrict__ out) {
    const int tid = threadIdx.x;
    __shared__ float r[512];

    r[tid] = g_row_supin[tid]; __syncthreads();
    for (int o = 256; o > 0; o >>= 1) { if (tid < o) r[tid] += r[tid + o]; __syncthreads(); }
    if (tid == 0) out[0] = r[0] / (float)Bsz;
    __syncthreads();

    r[tid] = g_row_fc[tid]; __syncthreads();
    for (int o = 256; o > 0; o >>= 1) { if (tid < o) r[tid] += r[tid + o]; __syncthreads(); }
    if (tid == 0) out[1] = -r[0] / (float)Bsz;
    __syncthreads();

    r[tid] = g_row_dc[tid]; __syncthreads();
    for (int o = 256; o > 0; o >>= 1) { if (tid < o) r[tid] += r[tid + o]; __syncthreads(); }
    if (tid == 0) out[2] = r[0] / (float)Bsz;
}

// ---------------------------------------------------------------------------
extern "C" void kernel_launch(void* const* d_in, const int* in_sizes, int n_in,
                              void* d_out, int out_size)
{
    const float* normq  = (const float*)d_in[0];
    const float* qlog   = (const float*)d_in[1];
    const float* kfeat  = (const float*)d_in[2];
    // d_in[3] = logits_k (unused)
    const float* queue  = (const float*)d_in[4];
    const float* qlp    = (const float*)d_in[5];
    const void*  qlabel = d_in[6];
    const void*  target = d_in[7];
    const int*   knnk   = (const int*)d_in[8];
    float* out = (float*)d_out;

    const int SMEM1 = 2 * STG1 * 4;  // 80 KB
    const int SMEM2 = 2 * STG2 * 4;  // 72 KB
    cudaFuncSetAttribute(gemm1_mma, cudaFuncAttributeMaxDynamicSharedMemorySize, SMEM1);
    cudaFuncSetAttribute(gemm2_mma, cudaFuncAttributeMaxDynamicSharedMemorySize, SMEM2);

    // order: gemm1 is the 4th launch (the one ncu captures)
    convAQ_kernel<<<8448, 256>>>(normq, kfeat, queue);
    convP_kernel<<<dim3(32, 1024), 256>>>(qlp);
    detect_kernel<<<1, 32>>>((const int*)qlabel);
    gemm1_mma<<<dim3(512, 8), 256, SMEM1>>>();
    gemm2_mma<<<dim3(8, 4, 16), 256, SMEM2>>>();
    supcon_kernel<<<512, 256>>>(qlabel, target, knnk);
    invz_kernel<<<512, 256>>>();
    fcdc_kernel<<<512, 256>>>(qlog, target);
    finalize_kernel<<<1, 512>>>(out);
    (void)in_sizes; (void)n_in; (void)out_size;
}

// round 8
// speedup vs baseline: 1.8189x; 1.0785x over previous
#include <cuda_runtime.h>
#include <cuda_bf16.h>
#include <cstdint>

// Problem constants
#define Bsz 512
#define Dd  256
#define Kq  65536
#define Cc  1000
#define Cpad 1024
#define T_SUPf 0.07f
#define T_DCf  0.1f
#define LSm  0.1f
#define EPSf 1e-8f
#define SPLIT2 16
#define PADW2 36  // gemm2: 32 bf16-pair words + 4 pad
#define PADW3 36  // gemm1: 32 fp32 words + 4 pad (stride 36 mod 32 = 4, conflict-free)

// -------- scratch (static device globals) ----------
__device__ float g_sim[(size_t)512 * Kq];
__device__ __align__(16) __nv_bfloat16 g_Ehi[(size_t)512 * Kq];
__device__ __align__(16) float g_Af[(size_t)1024 * Dd];    // cvt.rna'd [normq;kfeat]
__device__ __align__(16) float g_QTf[(size_t)Kq * Dd];     // cvt.rna'd queue^T
__device__ __align__(16) __nv_bfloat16 g_Phi[(size_t)Cpad * Kq];
__device__ float g_psum[(size_t)512 * 2048];
__device__ float g_part[(size_t)SPLIT2 * 512 * Cpad];
__device__ float g_invZ[512];
__device__ float g_row_supin[512];
__device__ float g_row_fc[512];
__device__ float g_row_dc[512];
__device__ int   g_is64;

// ---------------- helpers ----------------
__device__ __forceinline__ uint32_t smem_u32(const void* p) {
    uint32_t a;
    asm("{ .reg .u64 t; cvta.to.shared.u64 t, %1; cvt.u32.u64 %0, t; }" : "=r"(a) : "l"(p));
    return a;
}
__device__ __forceinline__ void cp16(uint32_t dst, const void* src) {
    asm volatile("cp.async.cg.shared.global [%0], [%1], 16;\n" :: "r"(dst), "l"(src));
}
#define CPCOMMIT() asm volatile("cp.async.commit_group;\n" ::: "memory")
#define CPWAIT0()  asm volatile("cp.async.wait_group 0;\n" ::: "memory")

__device__ __forceinline__ void mma_bf16(float* c, uint32_t a0, uint32_t a1,
                                         uint32_t a2, uint32_t a3,
                                         uint32_t b0, uint32_t b1) {
    asm volatile(
        "mma.sync.aligned.m16n8k16.row.col.f32.bf16.bf16.f32 "
        "{%0,%1,%2,%3}, {%4,%5,%6,%7}, {%8,%9}, {%0,%1,%2,%3};\n"
        : "+f"(c[0]), "+f"(c[1]), "+f"(c[2]), "+f"(c[3])
        : "r"(a0), "r"(a1), "r"(a2), "r"(a3), "r"(b0), "r"(b1));
}
__device__ __forceinline__ void mma_tf32(float* c, uint32_t a0, uint32_t a1,
                                         uint32_t a2, uint32_t a3,
                                         uint32_t b0, uint32_t b1) {
    asm volatile(
        "mma.sync.aligned.m16n8k8.row.col.f32.tf32.tf32.f32 "
        "{%0,%1,%2,%3}, {%4,%5,%6,%7}, {%8,%9}, {%0,%1,%2,%3};\n"
        : "+f"(c[0]), "+f"(c[1]), "+f"(c[2]), "+f"(c[3])
        : "r"(a0), "r"(a1), "r"(a2), "r"(a3), "r"(b0), "r"(b1));
}

__device__ __forceinline__ float tf32r(float f) {
    uint32_t u;
    asm("cvt.rna.tf32.f32 %0, %1;" : "=r"(u) : "f"(f));
    return __uint_as_float(u);
}
__device__ __forceinline__ uint32_t pack_bf16(float f0, float f1) {
    return ((uint32_t)__bfloat16_as_ushort(__float2bfloat16(f1)) << 16)
         | (uint32_t)__bfloat16_as_ushort(__float2bfloat16(f0));
}
__device__ __forceinline__ unsigned fmap(float f) {
    unsigned u = __float_as_uint(f);
    return (u & 0x80000000u) ? ~u : (u | 0x80000000u);
}

// ---------------------------------------------------------------------------
__global__ void detect_kernel(const int* __restrict__ qlabel_raw) {
    if (threadIdx.x == 0 && blockIdx.x == 0) {
        int is64 = 1;
        for (int i = 0; i < 4096; i++) {
            if (qlabel_raw[2 * i + 1] != 0) { is64 = 0; break; }
        }
        g_is64 = is64;
    }
}
__device__ __forceinline__ long long load_label(const void* p, int i) {
    if (g_is64) return ((const long long*)p)[i];
    return (long long)((const int*)p)[i];
}

// ---------------------------------------------------------------------------
// convAQ: blocks [0,8192): queue transpose + cvt.rna -> g_QTf
//         blocks [8192,8448): [normq;kfeat] cvt.rna -> g_Af
// ---------------------------------------------------------------------------
__global__ void __launch_bounds__(256) convAQ_kernel(
    const float* __restrict__ nq, const float* __restrict__ kf,
    const float* __restrict__ Q)
{
    const int t = threadIdx.x;
    if (blockIdx.x < 8192) {
        __shared__ float s[32][65];
        const int n0 = (blockIdx.x & 2047) * 32, d0 = (blockIdx.x >> 11) * 64;
        const int nl = t & 31, dl = t >> 5;
        #pragma unroll
        for (int i = 0; i < 8; i++) {
            int d = i * 8 + dl;
            s[nl][d] = Q[(size_t)(d0 + d) * Kq + n0 + nl];
        }
        __syncthreads();
        const int n = t >> 3, dq = (t & 7) * 8;
        float v[8];
        #pragma unroll
        for (int j = 0; j < 8; j++) v[j] = tf32r(s[n][dq + j]);
        size_t off = (size_t)(n0 + n) * Dd + d0 + dq;
        *(float4*)(g_QTf + off)     = make_float4(v[0], v[1], v[2], v[3]);
        *(float4*)(g_QTf + off + 4) = make_float4(v[4], v[5], v[6], v[7]);
    } else {
        size_t i = ((size_t)(blockIdx.x - 8192) * 256 + t) * 4;
        const size_t half = (size_t)512 * Dd;
        const float* src = (i < half) ? (nq + i) : (kf + (i - half));
        float4 v = *(const float4*)src;
        *(float4*)(g_Af + i) = make_float4(tf32r(v.x), tf32r(v.y), tf32r(v.z), tf32r(v.w));
    }
}

// ---------------------------------------------------------------------------
// convP: P [1000][65536] fp32 -> Phi bf16 (rows >= 1000 zero)
// ---------------------------------------------------------------------------
__global__ void __launch_bounds__(256) convP_kernel(const float* __restrict__ P) {
    const int c = blockIdx.y;
    const size_t k = (size_t)blockIdx.x * 2048 + threadIdx.x * 8;
    size_t off = (size_t)c * Kq + k;
    uint32_t hi[4];
    if (c < Cc) {
        float4 v0 = *(const float4*)(P + off);
        float4 v1 = *(const float4*)(P + off + 4);
        hi[0] = pack_bf16(v0.x, v0.y);
        hi[1] = pack_bf16(v0.z, v0.w);
        hi[2] = pack_bf16(v1.x, v1.y);
        hi[3] = pack_bf16(v1.z, v1.w);
    } else {
        hi[0] = hi[1] = hi[2] = hi[3] = 0u;
    }
    *(uint4*)(g_Phi + off) = make_uint4(hi[0], hi[1], hi[2], hi[3]);
}

// ---------------------------------------------------------------------------
// GEMM1 v3 (tf32 single-pass): CTA 128x128, kc=32, 2-stage.
// Stage: A 128x36 fp32 + B 128x36 fp32 = 36 KB; 2 stages = 72 KB -> 2 CTA/SM.
// grid (mt=8, nt=512) -- mt fastest so concurrent CTAs share the B tile.
// ---------------------------------------------------------------------------
#define STG1 (128 * PADW3 * 2)   // words per stage (A+B)

__device__ __forceinline__ void g1_load(uint32_t sbase, int buf,
    const float* A, const float* B, int kc, int tid)
{
    const int r = tid >> 1;
    const int c0 = (tid & 1) * 4;
    const uint32_t so = sbase + (uint32_t)buf * (STG1 * 4);
    const uint32_t sB = so + 128 * PADW3 * 4;
    #pragma unroll
    for (int i = 0; i < 4; i++) {
        int c = c0 + i;
        uint32_t off = (uint32_t)(r * PADW3 + c * 4) * 4;
        size_t goff = (size_t)r * Dd + kc + c * 4;
        cp16(so + off, A + goff);
        cp16(sB + off, B + goff);
    }
}

__device__ __forceinline__ void g1_compute(const uint32_t* sm, int buf,
    float acc[4][4][4], int wm, int wn, int g, int tig)
{
    const uint32_t* Ap = sm + buf * STG1;
    const uint32_t* Bp = Ap + 128 * PADW3;
    #pragma unroll
    for (int ks = 0; ks < 4; ks++) {
        const int kb = ks * 8;
        uint32_t bb[4][2];
        #pragma unroll
        for (int n = 0; n < 4; n++) {
            int nr = wn * 32 + n * 8 + g;
            bb[n][0] = Bp[nr * PADW3 + kb + tig];
            bb[n][1] = Bp[nr * PADW3 + kb + tig + 4];
        }
        #pragma unroll
        for (int m = 0; m < 4; m++) {
            int r0 = wm * 64 + m * 16 + g, r1 = r0 + 8;
            uint32_t a0 = Ap[r0 * PADW3 + kb + tig];
            uint32_t a1 = Ap[r1 * PADW3 + kb + tig];
            uint32_t a2 = Ap[r0 * PADW3 + kb + tig + 4];
            uint32_t a3 = Ap[r1 * PADW3 + kb + tig + 4];
            #pragma unroll
            for (int n = 0; n < 4; n++)
                mma_tf32(acc[m][n], a0, a1, a2, a3, bb[n][0], bb[n][1]);
        }
    }
}

__global__ void __launch_bounds__(256, 2) gemm1_mma() {
    extern __shared__ __align__(16) uint32_t sm[];
    const int mt = blockIdx.x;   // 0..7 (fastest: shares B tile)
    const int nt = blockIdx.y;   // 0..511
    const int tid = threadIdx.x;
    const int lane = tid & 31, wid = tid >> 5;
    const int wm = wid >> 2, wn = wid & 3;
    const int g = lane >> 2, tig = lane & 3;
    const uint32_t sbase = smem_u32(sm);

    const float* A = g_Af + (size_t)mt * 128 * Dd;
    const float* B = g_QTf + (size_t)nt * 128 * Dd;

    float acc[4][4][4] = {};
    const int NS = Dd / 32;   // 8

    g1_load(sbase, 0, A, B, 0, tid);
    CPCOMMIT();
    for (int s = 0; s < NS; s++) {
        CPWAIT0();
        __syncthreads();
        if (s + 1 < NS) {
            g1_load(sbase, (s + 1) & 1, A, B, (s + 1) * 32, tid);
            CPCOMMIT();
        }
        g1_compute(sm, s & 1, acc, wm, wn, g, tig);
    }

    const int rbase = mt * 128 + wm * 64;
    const int col = nt * 128 + wn * 32;
    if (mt < 4) {
        #pragma unroll
        for (int m = 0; m < 4; m++) {
            int r0 = rbase + m * 16 + g;
            #pragma unroll
            for (int n = 0; n < 4; n++) {
                int c = col + n * 8 + tig * 2;
                *(float2*)&g_sim[(size_t)r0 * Kq + c] = make_float2(acc[m][n][0], acc[m][n][1]);
                *(float2*)&g_sim[(size_t)(r0 + 8) * Kq + c] = make_float2(acc[m][n][2], acc[m][n][3]);
            }
        }
    } else {
        #pragma unroll
        for (int m = 0; m < 4; m++) {
            int b0 = rbase - 512 + m * 16 + g;
            float s0 = 0.f, s1 = 0.f;
            #pragma unroll
            for (int n = 0; n < 4; n++) {
                int c = col + n * 8 + tig * 2;
                float e0 = __expf(acc[m][n][0] * (1.0f / T_DCf));
                float e1 = __expf(acc[m][n][1] * (1.0f / T_DCf));
                float e2 = __expf(acc[m][n][2] * (1.0f / T_DCf));
                float e3 = __expf(acc[m][n][3] * (1.0f / T_DCf));
                *(uint32_t*)&g_Ehi[(size_t)b0 * Kq + c] = pack_bf16(e0, e1);
                *(uint32_t*)&g_Ehi[(size_t)(b0 + 8) * Kq + c] = pack_bf16(e2, e3);
                s0 += e0 + e1;
                s1 += e2 + e3;
            }
            s0 += __shfl_xor_sync(0xffffffffu, s0, 1);
            s0 += __shfl_xor_sync(0xffffffffu, s0, 2);
            s1 += __shfl_xor_sync(0xffffffffu, s1, 1);
            s1 += __shfl_xor_sync(0xffffffffu, s1, 2);
            if (tig == 0) {
                g_psum[(size_t)b0 * 2048 + nt * 4 + wn] = s0;
                g_psum[(size_t)(b0 + 8) * 2048 + nt * 4 + wn] = s1;
            }
        }
    }
}

// ---------------------------------------------------------------------------
// GEMM2 (1-term Eh x Ph, R7-proven): CTA 128x128, kc=64, 2-stage, SPLIT2=16.
// grid (sp=16, mt=4, nt=8): sp fastest -> every tile streamed ~once; E stays
// L2-resident across nt re-reads.
// ---------------------------------------------------------------------------
#define STG2 (128 * PADW2 * 2)
#define ABLK (128 * PADW2 * 4)

__device__ __forceinline__ void g2_load(uint32_t sbase, int buf,
    const __nv_bfloat16* Ah, const __nv_bfloat16* Bh, int kc, int tid)
{
    const int r = tid >> 1;
    const int c0 = (tid & 1) * 4;
    const uint32_t so = sbase + (uint32_t)buf * (STG2 * 4);
    #pragma unroll
    for (int i = 0; i < 4; i++) {
        int c = c0 + i;
        uint32_t off = (uint32_t)(r * PADW2 + c * 4) * 4;
        size_t goff = (size_t)r * Kq + kc + c * 8;
        cp16(so + off,        Ah + goff);
        cp16(so + ABLK + off, Bh + goff);
    }
}

__device__ __forceinline__ void g2_compute(const uint32_t* sm, int buf,
    float acc[4][4][4], int wm, int wn, int g, int tig)
{
    const uint32_t* Ap = sm + buf * STG2;
    const uint32_t* Bp = Ap + 128 * PADW2;
    #pragma unroll
    for (int ks = 0; ks < 4; ks++) {
        const int w = ks * 8 + tig;
        uint32_t ah[4][4];
        #pragma unroll
        for (int m = 0; m < 4; m++) {
            int r0 = wm * 64 + m * 16 + g, r1 = r0 + 8;
            ah[m][0] = Ap[r0 * PADW2 + w];     ah[m][1] = Ap[r1 * PADW2 + w];
            ah[m][2] = Ap[r0 * PADW2 + w + 4]; ah[m][3] = Ap[r1 * PADW2 + w + 4];
        }
        #pragma unroll
        for (int n = 0; n < 4; n++) {
            int nr = wn * 32 + n * 8 + g;
            uint32_t b0 = Bp[nr * PADW2 + w], b1 = Bp[nr * PADW2 + w + 4];
            #pragma unroll
            for (int m = 0; m < 4; m++)
                mma_bf16(acc[m][n], ah[m][0], ah[m][1], ah[m][2], ah[m][3], b0, b1);
        }
    }
}

__global__ void __launch_bounds__(256) gemm2_mma() {
    extern __shared__ __align__(16) uint32_t sm[];
    const int sp = blockIdx.x;   // 0..15 (fastest)
    const int mt = blockIdx.y;   // 0..3
    const int nt = blockIdx.z;   // 0..7
    const int tid = threadIdx.x;
    const int lane = tid & 31, wid = tid >> 5;
    const int wm = wid >> 2, wn = wid & 3;
    const int g = lane >> 2, tig = lane & 3;
    const uint32_t sbase = smem_u32(sm);

    const size_t k0 = (size_t)sp * (Kq / SPLIT2);
    const __nv_bfloat16* Ah = g_Ehi + (size_t)mt * 128 * Kq + k0;
    const __nv_bfloat16* Bh = g_Phi + (size_t)nt * 128 * Kq + k0;

    float acc[4][4][4] = {};
    const int NS = (Kq / SPLIT2) / 64;   // 64

    g2_load(sbase, 0, Ah, Bh, 0, tid);
    CPCOMMIT();
    for (int s = 0; s < NS; s++) {
        CPWAIT0();
        __syncthreads();
        if (s + 1 < NS) {
            g2_load(sbase, (s + 1) & 1, Ah, Bh, (s + 1) * 64, tid);
            CPCOMMIT();
        }
        g2_compute(sm, s & 1, acc, wm, wn, g, tig);
    }

    #pragma unroll
    for (int m = 0; m < 4; m++) {
        int b = mt * 128 + wm * 64 + m * 16 + g;
        #pragma unroll
        for (int n = 0; n < 4; n++) {
            int c = nt * 128 + wn * 32 + n * 8 + tig * 2;
            *(float2*)&g_part[((size_t)sp * 512 + b) * Cpad + c] =
                make_float2(acc[m][n][0], acc[m][n][1]);
            *(float2*)&g_part[((size_t)sp * 512 + b + 8) * Cpad + c] =
                make_float2(acc[m][n][2], acc[m][n][3]);
        }
    }
}

// ---------------------------------------------------------------------------
// invz / supcon / fcdc / finalize (unchanged)
// ---------------------------------------------------------------------------
__global__ void __launch_bounds__(256) invz_kernel() {
    const int b = blockIdx.x;
    const int tid = threadIdx.x;
    float s = 0.f;
    for (int i = tid; i < 2048; i += 256) s += g_psum[(size_t)b * 2048 + i];
    __shared__ float red[256];
    red[tid] = s;
    __syncthreads();
    for (int o = 128; o > 0; o >>= 1) {
        if (tid < o) red[tid] += red[tid + o];
        __syncthreads();
    }
    if (tid == 0) g_invZ[b] = 1.0f / red[0];
}

#define MAXTIES 2048
__global__ void __launch_bounds__(256) supcon_kernel(
    const void* __restrict__ qlabel,
    const void* __restrict__ target,
    const int*  __restrict__ knnk)
{
    const int b = blockIdx.x;
    const float* row = g_sim + (size_t)b * Kq;
    const int tid = threadIdx.x;
    const int NT = 256;
    const int kneed = knnk[0];

    __shared__ unsigned hist[256];
    __shared__ unsigned s_prefix, s_desired;
    __shared__ int s_ties;
    __shared__ int tie_idx[MAXTIES];
    __shared__ float ra[256], rp[256];

    if (tid == 0) { s_prefix = 0; s_desired = (unsigned)kneed; }
    __syncthreads();

    for (int pass = 0; pass < 4; pass++) {
        const int shift = 24 - pass * 8;
        for (int i = tid; i < 256; i += NT) hist[i] = 0;
        __syncthreads();
        const unsigned pref = s_prefix;
        for (int k = tid; k < Kq; k += NT) {
            unsigned u = fmap(row[k]);
            bool ok = (pass == 0) || ((u >> (shift + 8)) == pref);
            if (ok) atomicAdd(&hist[(u >> shift) & 255u], 1u);
        }
        __syncthreads();
        if (tid == 0) {
            unsigned des = s_desired;
            for (int bin = 255; bin >= 0; bin--) {
                unsigned c = hist[bin];
                if (c >= des) {
                    s_prefix = (pref << 8) | (unsigned)bin;
                    s_desired = des;
                    break;
                }
                des -= c;
            }
        }
        __syncthreads();
    }

    const unsigned u200 = s_prefix;
    const unsigned des = s_desired;
    if (tid == 0) s_ties = 0;
    __syncthreads();

    float sa = 0.f, sp = 0.f;
    const long long tgt = load_label(target, b);
    for (int k = tid; k < Kq; k += NT) {
        float sv = row[k];
        unsigned u = fmap(sv);
        if (u > u200) {
            float e = __expf(sv * (1.0f / T_SUPf));
            sa += e;
            if (load_label(qlabel, k) == tgt) sp += e;
        } else if (u == u200) {
            int p = atomicAdd(&s_ties, 1);
            if (p < MAXTIES) tie_idx[p] = k;
        }
    }
    ra[tid] = sa; rp[tid] = sp;
    __syncthreads();
    for (int o = 128; o > 0; o >>= 1) {
        if (tid < o) { ra[tid] += ra[tid + o]; rp[tid] += rp[tid + o]; }
        __syncthreads();
    }

    if (tid == 0) {
        float SA = ra[0], SP = rp[0];
        int t = min(s_ties, MAXTIES);
        for (int i = 1; i < t; i++) {
            int v = tie_idx[i]; int j = i - 1;
            while (j >= 0 && tie_idx[j] > v) { tie_idx[j + 1] = tie_idx[j]; j--; }
            tie_idx[j + 1] = v;
        }
        int take = min((int)des, t);
        for (int i = 0; i < take; i++) {
            int k = tie_idx[i];
            float e = __expf(row[k] * (1.0f / T_SUPf));
            SA += e;
            if (load_label(qlabel, k) == tgt) SP += e;
        }
        float gt = SP / SA;
        g_row_supin[b] = (gt > EPSf) ? (-__logf(gt)) : 0.0f;
    }
}

__global__ void __launch_bounds__(256) fcdc_kernel(
    const float* __restrict__ qlog,
    const void* __restrict__ target)
{
    const int b = blockIdx.x;
    const int tid = threadIdx.x;
    const float* q = qlog + (size_t)b * Cc;
    __shared__ float red[256];

    float mx = -3.4e38f;
    for (int c = tid; c < Cc; c += 256) mx = fmaxf(mx, q[c]);
    red[tid] = mx; __syncthreads();
    for (int o = 128; o > 0; o >>= 1) { if (tid < o) red[tid] = fmaxf(red[tid], red[tid + o]); __syncthreads(); }
    const float Mx = red[0]; __syncthreads();

    float mn = 3.4e38f;
    for (int c = tid; c < Cc; c += 256) mn = fminf(mn, q[c]);
    red[tid] = mn; __syncthreads();
    for (int o = 128; o > 0; o >>= 1) { if (tid < o) red[tid] = fminf(red[tid], red[tid + o]); __syncthreads(); }
    const float Mn = red[0]; __syncthreads();

    float se = 0.f;
    for (int c = tid; c < Cc; c += 256) se += __expf(q[c] - Mx);
    red[tid] = se; __syncthreads();
    for (int o = 128; o > 0; o >>= 1) { if (tid < o) red[tid] += red[tid + o]; __syncthreads(); }
    const float SE = red[0]; __syncthreads();

    const float logZ = __logf(SE);
    const bool qmask = (__expf(Mn - Mx) / SE) > EPSf;
    const float invZk = g_invZ[b];
    const long long t = load_label(target, b);

    float fcs = 0.f, kl = 0.f;
    for (int c = tid; c < Cc; c += 256) {
        float lq = q[c] - Mx - logZ;
        float oh = (c == (int)t) ? (1.0f - LSm) : (LSm / (float)(Cc - 1));
        fcs += oh * lq;
        float ps = 0.f;
        #pragma unroll
        for (int s = 0; s < SPLIT2; s++)
            ps += g_part[((size_t)s * 512 + b) * Cpad + c];
        float dct = invZk * ps;
        if (dct > 0.f) kl += dct * (__logf(dct) - lq);
    }
    red[tid] = fcs; __syncthreads();
    for (int o = 128; o > 0; o >>= 1) { if (tid < o) red[tid] += red[tid + o]; __syncthreads(); }
    const float FCS = red[0]; __syncthreads();
    red[tid] = kl; __syncthreads();
    for (int o = 128; o > 0; o >>= 1) { if (tid < o) red[tid] += red[tid + o]; __syncthreads(); }
    if (tid == 0) {
        g_row_fc[b] = qmask ? FCS : 0.f;
        g_row_dc[b] = qmask ? red[0] : 0.f;
    }
}

__global__ void __launch_bounds__(512) finalize_kernel(float* __restrict__ out) {
    const int tid = threadIdx.x;
    __shared__ float r[512];

    r[tid] = g_row_supin[tid]; __syncthreads();
    for (int o = 256; o > 0; o >>= 1) { if (tid < o) r[tid] += r[tid + o]; __syncthreads(); }
    if (tid == 0) out[0] = r[0] / (float)Bsz;
    __syncthreads();

    r[tid] = g_row_fc[tid]; __syncthreads();
    for (int o = 256; o > 0; o >>= 1) { if (tid < o) r[tid] += r[tid + o]; __syncthreads(); }
    if (tid == 0) out[1] = -r[0] / (float)Bsz;
    __syncthreads();

    r[tid] = g_row_dc[tid]; __syncthreads();
    for (int o = 256; o > 0; o >>= 1) { if (tid < o) r[tid] += r[tid + o]; __syncthreads(); }
    if (tid == 0) out[2] = r[0] / (float)Bsz;
}

// ---------------------------------------------------------------------------
extern "C" void kernel_launch(void* const* d_in, const int* in_sizes, int n_in,
                              void* d_out, int out_size)
{
    const float* normq  = (const float*)d_in[0];
    const float* qlog   = (const float*)d_in[1];
    const float* kfeat  = (const float*)d_in[2];
    // d_in[3] = logits_k (unused)
    const float* queue  = (const float*)d_in[4];
    const float* qlp    = (const float*)d_in[5];
    const void*  qlabel = d_in[6];
    const void*  target = d_in[7];
    const int*   knnk   = (const int*)d_in[8];
    float* out = (float*)d_out;

    const int SMEM1 = 2 * STG1 * 4;  // 72 KB
    const int SMEM2 = 2 * STG2 * 4;  // 72 KB
    cudaFuncSetAttribute(gemm1_mma, cudaFuncAttributeMaxDynamicSharedMemorySize, SMEM1);
    cudaFuncSetAttribute(gemm2_mma, cudaFuncAttributeMaxDynamicSharedMemorySize, SMEM2);

    // order: gemm1 is the 4th launch (the one ncu captures)
    convAQ_kernel<<<8448, 256>>>(normq, kfeat, queue);
    convP_kernel<<<dim3(32, 1024), 256>>>(qlp);
    detect_kernel<<<1, 32>>>((const int*)qlabel);
    gemm1_mma<<<dim3(8, 512), 256, SMEM1>>>();
    gemm2_mma<<<dim3(16, 4, 8), 256, SMEM2>>>();
    supcon_kernel<<<512, 256>>>(qlabel, target, knnk);
    invz_kernel<<<512, 256>>>();
    fcdc_kernel<<<512, 256>>>(qlog, target);
    finalize_kernel<<<1, 512>>>(out);
    (void)in_sizes; (void)n_in; (void)out_size;
}

// round 9
// speedup vs baseline: 2.0297x; 1.1159x over previous
#include <cuda_runtime.h>
#include <cuda_bf16.h>
#include <cstdint>

// Problem constants
#define Bsz 512
#define Dd  256
#define Kq  65536
#define Cc  1000
#define Cpad 1024
#define T_SUPf 0.07f
#define T_DCf  0.1f
#define LSm  0.1f
#define EPSf 1e-8f
#define SPLIT2 9
#define PADW2 36  // gemm2: 32 bf16-pair words + 4 pad
#define PADW3 36  // gemm1: 32 fp32 words + 4 pad

// -------- scratch (static device globals) ----------
__device__ float g_sim[(size_t)512 * Kq];
__device__ __align__(16) __nv_bfloat16 g_Ehi[(size_t)512 * Kq];
__device__ __align__(16) float g_Af[(size_t)1024 * Dd];
__device__ __align__(16) float g_QTf[(size_t)Kq * Dd];
__device__ __align__(16) __nv_bfloat16 g_Phi[(size_t)Cpad * Kq];
__device__ float g_psum[(size_t)512 * 2048];
__device__ float g_part[(size_t)SPLIT2 * 512 * Cpad];
__device__ float g_invZ[512];
__device__ float g_row_supin[512];
__device__ float g_row_fc[512];
__device__ float g_row_dc[512];
__device__ int   g_is64;

// ---------------- helpers ----------------
__device__ __forceinline__ uint32_t smem_u32(const void* p) {
    uint32_t a;
    asm("{ .reg .u64 t; cvta.to.shared.u64 t, %1; cvt.u32.u64 %0, t; }" : "=r"(a) : "l"(p));
    return a;
}
__device__ __forceinline__ void cp16(uint32_t dst, const void* src) {
    asm volatile("cp.async.cg.shared.global [%0], [%1], 16;\n" :: "r"(dst), "l"(src));
}
#define CPCOMMIT() asm volatile("cp.async.commit_group;\n" ::: "memory")
#define CPWAIT0()  asm volatile("cp.async.wait_group 0;\n" ::: "memory")

__device__ __forceinline__ void mma_bf16(float* c, uint32_t a0, uint32_t a1,
                                         uint32_t a2, uint32_t a3,
                                         uint32_t b0, uint32_t b1) {
    asm volatile(
        "mma.sync.aligned.m16n8k16.row.col.f32.bf16.bf16.f32 "
        "{%0,%1,%2,%3}, {%4,%5,%6,%7}, {%8,%9}, {%0,%1,%2,%3};\n"
        : "+f"(c[0]), "+f"(c[1]), "+f"(c[2]), "+f"(c[3])
        : "r"(a0), "r"(a1), "r"(a2), "r"(a3), "r"(b0), "r"(b1));
}
__device__ __forceinline__ void mma_tf32(float* c, uint32_t a0, uint32_t a1,
                                         uint32_t a2, uint32_t a3,
                                         uint32_t b0, uint32_t b1) {
    asm volatile(
        "mma.sync.aligned.m16n8k8.row.col.f32.tf32.tf32.f32 "
        "{%0,%1,%2,%3}, {%4,%5,%6,%7}, {%8,%9}, {%0,%1,%2,%3};\n"
        : "+f"(c[0]), "+f"(c[1]), "+f"(c[2]), "+f"(c[3])
        : "r"(a0), "r"(a1), "r"(a2), "r"(a3), "r"(b0), "r"(b1));
}

__device__ __forceinline__ float tf32r(float f) {
    uint32_t u;
    asm("cvt.rna.tf32.f32 %0, %1;" : "=r"(u) : "f"(f));
    return __uint_as_float(u);
}
__device__ __forceinline__ uint32_t pack_bf16(float f0, float f1) {
    return ((uint32_t)__bfloat16_as_ushort(__float2bfloat16(f1)) << 16)
         | (uint32_t)__bfloat16_as_ushort(__float2bfloat16(f0));
}
__device__ __forceinline__ unsigned fmap(float f) {
    unsigned u = __float_as_uint(f);
    return (u & 0x80000000u) ? ~u : (u | 0x80000000u);
}

// ---------------------------------------------------------------------------
__global__ void detect_kernel(const int* __restrict__ qlabel_raw) {
    if (threadIdx.x == 0 && blockIdx.x == 0) {
        int is64 = 1;
        for (int i = 0; i < 4096; i++) {
            if (qlabel_raw[2 * i + 1] != 0) { is64 = 0; break; }
        }
        g_is64 = is64;
    }
}
__device__ __forceinline__ long long load_label(const void* p, int i) {
    if (g_is64) return ((const long long*)p)[i];
    return (long long)((const int*)p)[i];
}

// ---------------------------------------------------------------------------
// convAQ: queue transpose + tf32 round; [normq;kfeat] tf32 round.
// ---------------------------------------------------------------------------
__global__ void __launch_bounds__(256) convAQ_kernel(
    const float* __restrict__ nq, const float* __restrict__ kf,
    const float* __restrict__ Q)
{
    const int t = threadIdx.x;
    if (blockIdx.x < 8192) {
        __shared__ float s[32][65];
        const int n0 = (blockIdx.x & 2047) * 32, d0 = (blockIdx.x >> 11) * 64;
        const int nl = t & 31, dl = t >> 5;
        #pragma unroll
        for (int i = 0; i < 8; i++) {
            int d = i * 8 + dl;
            s[nl][d] = Q[(size_t)(d0 + d) * Kq + n0 + nl];
        }
        __syncthreads();
        const int n = t >> 3, dq = (t & 7) * 8;
        float v[8];
        #pragma unroll
        for (int j = 0; j < 8; j++) v[j] = tf32r(s[n][dq + j]);
        size_t off = (size_t)(n0 + n) * Dd + d0 + dq;
        *(float4*)(g_QTf + off)     = make_float4(v[0], v[1], v[2], v[3]);
        *(float4*)(g_QTf + off + 4) = make_float4(v[4], v[5], v[6], v[7]);
    } else {
        size_t i = ((size_t)(blockIdx.x - 8192) * 256 + t) * 4;
        const size_t half = (size_t)512 * Dd;
        const float* src = (i < half) ? (nq + i) : (kf + (i - half));
        float4 v = *(const float4*)src;
        *(float4*)(g_Af + i) = make_float4(tf32r(v.x), tf32r(v.y), tf32r(v.z), tf32r(v.w));
    }
}

// ---------------------------------------------------------------------------
// convP: P -> Phi bf16
// ---------------------------------------------------------------------------
__global__ void __launch_bounds__(256) convP_kernel(const float* __restrict__ P) {
    const int c = blockIdx.y;
    const size_t k = (size_t)blockIdx.x * 2048 + threadIdx.x * 8;
    size_t off = (size_t)c * Kq + k;
    uint32_t hi[4];
    if (c < Cc) {
        float4 v0 = *(const float4*)(P + off);
        float4 v1 = *(const float4*)(P + off + 4);
        hi[0] = pack_bf16(v0.x, v0.y);
        hi[1] = pack_bf16(v0.z, v0.w);
        hi[2] = pack_bf16(v1.x, v1.y);
        hi[3] = pack_bf16(v1.z, v1.w);
    } else {
        hi[0] = hi[1] = hi[2] = hi[3] = 0u;
    }
    *(uint4*)(g_Phi + off) = make_uint4(hi[0], hi[1], hi[2], hi[3]);
}

// ---------------------------------------------------------------------------
// GEMM1 (tf32, R8-proven): CTA 128x128, kc=32, 2-stage, grid (mt=8, nt=512)
// ---------------------------------------------------------------------------
#define STG1 (128 * PADW3 * 2)

__device__ __forceinline__ void g1_load(uint32_t sbase, int buf,
    const float* A, const float* B, int kc, int tid)
{
    const int r = tid >> 1;
    const int c0 = (tid & 1) * 4;
    const uint32_t so = sbase + (uint32_t)buf * (STG1 * 4);
    const uint32_t sB = so + 128 * PADW3 * 4;
    #pragma unroll
    for (int i = 0; i < 4; i++) {
        int c = c0 + i;
        uint32_t off = (uint32_t)(r * PADW3 + c * 4) * 4;
        size_t goff = (size_t)r * Dd + kc + c * 4;
        cp16(so + off, A + goff);
        cp16(sB + off, B + goff);
    }
}

__device__ __forceinline__ void g1_compute(const uint32_t* sm, int buf,
    float acc[4][4][4], int wm, int wn, int g, int tig)
{
    const uint32_t* Ap = sm + buf * STG1;
    const uint32_t* Bp = Ap + 128 * PADW3;
    #pragma unroll
    for (int ks = 0; ks < 4; ks++) {
        const int kb = ks * 8;
        uint32_t bb[4][2];
        #pragma unroll
        for (int n = 0; n < 4; n++) {
            int nr = wn * 32 + n * 8 + g;
            bb[n][0] = Bp[nr * PADW3 + kb + tig];
            bb[n][1] = Bp[nr * PADW3 + kb + tig + 4];
        }
        #pragma unroll
        for (int m = 0; m < 4; m++) {
            int r0 = wm * 64 + m * 16 + g, r1 = r0 + 8;
            uint32_t a0 = Ap[r0 * PADW3 + kb + tig];
            uint32_t a1 = Ap[r1 * PADW3 + kb + tig];
            uint32_t a2 = Ap[r0 * PADW3 + kb + tig + 4];
            uint32_t a3 = Ap[r1 * PADW3 + kb + tig + 4];
            #pragma unroll
            for (int n = 0; n < 4; n++)
                mma_tf32(acc[m][n], a0, a1, a2, a3, bb[n][0], bb[n][1]);
        }
    }
}

__global__ void __launch_bounds__(256, 2) gemm1_mma() {
    extern __shared__ __align__(16) uint32_t sm[];
    const int mt = blockIdx.x;
    const int nt = blockIdx.y;
    const int tid = threadIdx.x;
    const int lane = tid & 31, wid = tid >> 5;
    const int wm = wid >> 2, wn = wid & 3;
    const int g = lane >> 2, tig = lane & 3;
    const uint32_t sbase = smem_u32(sm);

    const float* A = g_Af + (size_t)mt * 128 * Dd;
    const float* B = g_QTf + (size_t)nt * 128 * Dd;

    float acc[4][4][4] = {};
    const int NS = Dd / 32;

    g1_load(sbase, 0, A, B, 0, tid);
    CPCOMMIT();
    for (int s = 0; s < NS; s++) {
        CPWAIT0();
        __syncthreads();
        if (s + 1 < NS) {
            g1_load(sbase, (s + 1) & 1, A, B, (s + 1) * 32, tid);
            CPCOMMIT();
        }
        g1_compute(sm, s & 1, acc, wm, wn, g, tig);
    }

    const int rbase = mt * 128 + wm * 64;
    const int col = nt * 128 + wn * 32;
    if (mt < 4) {
        #pragma unroll
        for (int m = 0; m < 4; m++) {
            int r0 = rbase + m * 16 + g;
            #pragma unroll
            for (int n = 0; n < 4; n++) {
                int c = col + n * 8 + tig * 2;
                *(float2*)&g_sim[(size_t)r0 * Kq + c] = make_float2(acc[m][n][0], acc[m][n][1]);
                *(float2*)&g_sim[(size_t)(r0 + 8) * Kq + c] = make_float2(acc[m][n][2], acc[m][n][3]);
            }
        }
    } else {
        #pragma unroll
        for (int m = 0; m < 4; m++) {
            int b0 = rbase - 512 + m * 16 + g;
            float s0 = 0.f, s1 = 0.f;
            #pragma unroll
            for (int n = 0; n < 4; n++) {
                int c = col + n * 8 + tig * 2;
                float e0 = __expf(acc[m][n][0] * (1.0f / T_DCf));
                float e1 = __expf(acc[m][n][1] * (1.0f / T_DCf));
                float e2 = __expf(acc[m][n][2] * (1.0f / T_DCf));
                float e3 = __expf(acc[m][n][3] * (1.0f / T_DCf));
                *(uint32_t*)&g_Ehi[(size_t)b0 * Kq + c] = pack_bf16(e0, e1);
                *(uint32_t*)&g_Ehi[(size_t)(b0 + 8) * Kq + c] = pack_bf16(e2, e3);
                s0 += e0 + e1;
                s1 += e2 + e3;
            }
            s0 += __shfl_xor_sync(0xffffffffu, s0, 1);
            s0 += __shfl_xor_sync(0xffffffffu, s0, 2);
            s1 += __shfl_xor_sync(0xffffffffu, s1, 1);
            s1 += __shfl_xor_sync(0xffffffffu, s1, 2);
            if (tig == 0) {
                g_psum[(size_t)b0 * 2048 + nt * 4 + wn] = s0;
                g_psum[(size_t)(b0 + 8) * 2048 + nt * 4 + wn] = s1;
            }
        }
    }
}

// ---------------------------------------------------------------------------
// GEMM2 (1-term Eh x Ph): CTA 128x128, kc=64, 2-stage.
// SPLIT2=9 -> grid 9x4x8 = 288 CTAs <= 296 resident slots: ONE wave.
// Uneven k-ranges: stage s in [(sp*1024)/9, ((sp+1)*1024)/9), kc = s*64.
// ---------------------------------------------------------------------------
#define STG2 (128 * PADW2 * 2)
#define ABLK (128 * PADW2 * 4)

__device__ __forceinline__ void g2_load(uint32_t sbase, int buf,
    const __nv_bfloat16* Ah, const __nv_bfloat16* Bh, int kc, int tid)
{
    const int r = tid >> 1;
    const int c0 = (tid & 1) * 4;
    const uint32_t so = sbase + (uint32_t)buf * (STG2 * 4);
    #pragma unroll
    for (int i = 0; i < 4; i++) {
        int c = c0 + i;
        uint32_t off = (uint32_t)(r * PADW2 + c * 4) * 4;
        size_t goff = (size_t)r * Kq + kc + c * 8;
        cp16(so + off,        Ah + goff);
        cp16(so + ABLK + off, Bh + goff);
    }
}

__device__ __forceinline__ void g2_compute(const uint32_t* sm, int buf,
    float acc[4][4][4], int wm, int wn, int g, int tig)
{
    const uint32_t* Ap = sm + buf * STG2;
    const uint32_t* Bp = Ap + 128 * PADW2;
    #pragma unroll
    for (int ks = 0; ks < 4; ks++) {
        const int w = ks * 8 + tig;
        uint32_t ah[4][4];
        #pragma unroll
        for (int m = 0; m < 4; m++) {
            int r0 = wm * 64 + m * 16 + g, r1 = r0 + 8;
            ah[m][0] = Ap[r0 * PADW2 + w];     ah[m][1] = Ap[r1 * PADW2 + w];
            ah[m][2] = Ap[r0 * PADW2 + w + 4]; ah[m][3] = Ap[r1 * PADW2 + w + 4];
        }
        #pragma unroll
        for (int n = 0; n < 4; n++) {
            int nr = wn * 32 + n * 8 + g;
            uint32_t b0 = Bp[nr * PADW2 + w], b1 = Bp[nr * PADW2 + w + 4];
            #pragma unroll
            for (int m = 0; m < 4; m++)
                mma_bf16(acc[m][n], ah[m][0], ah[m][1], ah[m][2], ah[m][3], b0, b1);
        }
    }
}

__global__ void __launch_bounds__(256) gemm2_mma() {
    extern __shared__ __align__(16) uint32_t sm[];
    const int sp = blockIdx.x;   // 0..8
    const int mt = blockIdx.y;   // 0..3
    const int nt = blockIdx.z;   // 0..7
    const int tid = threadIdx.x;
    const int lane = tid & 31, wid = tid >> 5;
    const int wm = wid >> 2, wn = wid & 3;
    const int g = lane >> 2, tig = lane & 3;
    const uint32_t sbase = smem_u32(sm);

    const __nv_bfloat16* Ah = g_Ehi + (size_t)mt * 128 * Kq;
    const __nv_bfloat16* Bh = g_Phi + (size_t)nt * 128 * Kq;

    const int s0 = (sp * 1024) / SPLIT2;
    const int s1 = ((sp + 1) * 1024) / SPLIT2;

    float acc[4][4][4] = {};

    g2_load(sbase, 0, Ah, Bh, s0 * 64, tid);
    CPCOMMIT();
    for (int s = s0; s < s1; s++) {
        CPWAIT0();
        __syncthreads();
        if (s + 1 < s1) {
            g2_load(sbase, (s + 1 - s0) & 1, Ah, Bh, (s + 1) * 64, tid);
            CPCOMMIT();
        }
        g2_compute(sm, (s - s0) & 1, acc, wm, wn, g, tig);
    }

    #pragma unroll
    for (int m = 0; m < 4; m++) {
        int b = mt * 128 + wm * 64 + m * 16 + g;
        #pragma unroll
        for (int n = 0; n < 4; n++) {
            int c = nt * 128 + wn * 32 + n * 8 + tig * 2;
            *(float2*)&g_part[((size_t)sp * 512 + b) * Cpad + c] =
                make_float2(acc[m][n][0], acc[m][n][1]);
            *(float2*)&g_part[((size_t)sp * 512 + b + 8) * Cpad + c] =
                make_float2(acc[m][n][2], acc[m][n][3]);
        }
    }
}

// ---------------------------------------------------------------------------
// supcon v2 (2-pass):
// Pass 1: 4096-bin histogram on top-12 bits of fmap(sim) -> threshold bin T,
//         deficit `need` within T.
// Pass 2: accumulate exp for bins > T; collect bin==T candidates; bitonic sort
//         (value desc, index asc); take first `need`.
// ---------------------------------------------------------------------------
#define HBINS 4096
#define MAXC 2048
__global__ void __launch_bounds__(256) supcon_kernel(
    const void* __restrict__ qlabel,
    const void* __restrict__ target,
    const int*  __restrict__ knnk)
{
    const int b = blockIdx.x;
    const float* row = g_sim + (size_t)b * Kq;
    const int tid = threadIdx.x;
    const int NT = 256;
    const int kneed = knnk[0];

    __shared__ unsigned hist[HBINS];                 // 16 KB
    __shared__ unsigned long long ckey[MAXC];        // 16 KB
    __shared__ int s_cand, s_bin, s_need;
    __shared__ float ra[256], rp[256];

    // pass 1: histogram
    for (int i = tid; i < HBINS; i += NT) hist[i] = 0;
    if (tid == 0) s_cand = 0;
    __syncthreads();
    for (int k = tid; k < Kq; k += NT)
        atomicAdd(&hist[fmap(row[k]) >> 20], 1u);
    __syncthreads();
    if (tid == 0) {
        unsigned des = (unsigned)kneed;
        int bin = HBINS - 1;
        for (; bin >= 0; bin--) {
            unsigned c = hist[bin];
            if (c >= des) break;
            des -= c;
        }
        s_bin = bin;
        s_need = (int)des;
    }
    __syncthreads();
    const unsigned binT = (unsigned)s_bin;

    // pass 2: accumulate strict-above, collect in-bin candidates
    float sa = 0.f, sp = 0.f;
    const long long tgt = load_label(target, b);
    for (int k = tid; k < Kq; k += NT) {
        float sv = row[k];
        unsigned u = fmap(sv);
        unsigned ub = u >> 20;
        if (ub > binT) {
            float e = __expf(sv * (1.0f / T_SUPf));
            sa += e;
            if (load_label(qlabel, k) == tgt) sp += e;
        } else if (ub == binT) {
            int p = atomicAdd(&s_cand, 1);
            if (p < MAXC)
                ckey[p] = ((unsigned long long)(~u) << 32) | (unsigned)k;
        }
    }
    __syncthreads();

    // bitonic sort candidates ascending on (~u, idx) == (u desc, idx asc)
    const int cand = min(s_cand, MAXC);
    int n2 = 2;
    while (n2 < cand) n2 <<= 1;
    for (int i = cand + tid; i < n2; i += NT) ckey[i] = ~0ull;
    __syncthreads();
    for (int kk = 2; kk <= n2; kk <<= 1) {
        for (int j = kk >> 1; j > 0; j >>= 1) {
            for (int i = tid; i < n2; i += NT) {
                int ixj = i ^ j;
                if (ixj > i) {
                    unsigned long long a = ckey[i], c = ckey[ixj];
                    bool up = ((i & kk) == 0);
                    if ((a > c) == up) { ckey[i] = c; ckey[ixj] = a; }
                }
            }
            __syncthreads();
        }
    }

    // take first `need` candidates
    const int need = min(s_need, cand);
    for (int t2 = tid; t2 < need; t2 += NT) {
        int k = (int)(unsigned)(ckey[t2] & 0xFFFFFFFFull);
        float sv = row[k];
        float e = __expf(sv * (1.0f / T_SUPf));
        sa += e;
        if (load_label(qlabel, k) == tgt) sp += e;
    }

    ra[tid] = sa; rp[tid] = sp;
    __syncthreads();
    for (int o = 128; o > 0; o >>= 1) {
        if (tid < o) { ra[tid] += ra[tid + o]; rp[tid] += rp[tid + o]; }
        __syncthreads();
    }
    if (tid == 0) {
        float gt = rp[0] / ra[0];
        g_row_supin[b] = (gt > EPSf) ? (-__logf(gt)) : 0.0f;
    }
}

// ---------------------------------------------------------------------------
// invz / fcdc / finalize
// ---------------------------------------------------------------------------
__global__ void __launch_bounds__(256) invz_kernel() {
    const int b = blockIdx.x;
    const int tid = threadIdx.x;
    float s = 0.f;
    for (int i = tid; i < 2048; i += 256) s += g_psum[(size_t)b * 2048 + i];
    __shared__ float red[256];
    red[tid] = s;
    __syncthreads();
    for (int o = 128; o > 0; o >>= 1) {
        if (tid < o) red[tid] += red[tid + o];
        __syncthreads();
    }
    if (tid == 0) g_invZ[b] = 1.0f / red[0];
}

__global__ void __launch_bounds__(256) fcdc_kernel(
    const float* __restrict__ qlog,
    const void* __restrict__ target)
{
    const int b = blockIdx.x;
    const int tid = threadIdx.x;
    const float* q = qlog + (size_t)b * Cc;
    __shared__ float red[256];

    float mx = -3.4e38f;
    for (int c = tid; c < Cc; c += 256) mx = fmaxf(mx, q[c]);
    red[tid] = mx; __syncthreads();
    for (int o = 128; o > 0; o >>= 1) { if (tid < o) red[tid] = fmaxf(red[tid], red[tid + o]); __syncthreads(); }
    const float Mx = red[0]; __syncthreads();

    float mn = 3.4e38f;
    for (int c = tid; c < Cc; c += 256) mn = fminf(mn, q[c]);
    red[tid] = mn; __syncthreads();
    for (int o = 128; o > 0; o >>= 1) { if (tid < o) red[tid] = fminf(red[tid], red[tid + o]); __syncthreads(); }
    const float Mn = red[0]; __syncthreads();

    float se = 0.f;
    for (int c = tid; c < Cc; c += 256) se += __expf(q[c] - Mx);
    red[tid] = se; __syncthreads();
    for (int o = 128; o > 0; o >>= 1) { if (tid < o) red[tid] += red[tid + o]; __syncthreads(); }
    const float SE = red[0]; __syncthreads();

    const float logZ = __logf(SE);
    const bool qmask = (__expf(Mn - Mx) / SE) > EPSf;
    const float invZk = g_invZ[b];
    const long long t = load_label(target, b);

    float fcs = 0.f, kl = 0.f;
    for (int c = tid; c < Cc; c += 256) {
        float lq = q[c] - Mx - logZ;
        float oh = (c == (int)t) ? (1.0f - LSm) : (LSm / (float)(Cc - 1));
        fcs += oh * lq;
        float ps = 0.f;
        #pragma unroll
        for (int s = 0; s < SPLIT2; s++)
            ps += g_part[((size_t)s * 512 + b) * Cpad + c];
        float dct = invZk * ps;
        if (dct > 0.f) kl += dct * (__logf(dct) - lq);
    }
    red[tid] = fcs; __syncthreads();
    for (int o = 128; o > 0; o >>= 1) { if (tid < o) red[tid] += red[tid + o]; __syncthreads(); }
    const float FCS = red[0]; __syncthreads();
    red[tid] = kl; __syncthreads();
    for (int o = 128; o > 0; o >>= 1) { if (tid < o) red[tid] += red[tid + o]; __syncthreads(); }
    if (tid == 0) {
        g_row_fc[b] = qmask ? FCS : 0.f;
        g_row_dc[b] = qmask ? red[0] : 0.f;
    }
}

__global__ void __launch_bounds__(512) finalize_kernel(float* __restrict__ out) {
    const int tid = threadIdx.x;
    __shared__ float r[512];

    r[tid] = g_row_supin[tid]; __syncthreads();
    for (int o = 256; o > 0; o >>= 1) { if (tid < o) r[tid] += r[tid + o]; __syncthreads(); }
    if (tid == 0) out[0] = r[0] / (float)Bsz;
    __syncthreads();

    r[tid] = g_row_fc[tid]; __syncthreads();
    for (int o = 256; o > 0; o >>= 1) { if (tid < o) r[tid] += r[tid + o]; __syncthreads(); }
    if (tid == 0) out[1] = -r[0] / (float)Bsz;
    __syncthreads();

    r[tid] = g_row_dc[tid]; __syncthreads();
    for (int o = 256; o > 0; o >>= 1) { if (tid < o) r[tid] += r[tid + o]; __syncthreads(); }
    if (tid == 0) out[2] = r[0] / (float)Bsz;
}

// ---------------------------------------------------------------------------
extern "C" void kernel_launch(void* const* d_in, const int* in_sizes, int n_in,
                              void* d_out, int out_size)
{
    const float* normq  = (const float*)d_in[0];
    const float* qlog   = (const float*)d_in[1];
    const float* kfeat  = (const float*)d_in[2];
    // d_in[3] = logits_k (unused)
    const float* queue  = (const float*)d_in[4];
    const float* qlp    = (const float*)d_in[5];
    const void*  qlabel = d_in[6];
    const void*  target = d_in[7];
    const int*   knnk   = (const int*)d_in[8];
    float* out = (float*)d_out;

    const int SMEM1 = 2 * STG1 * 4;  // 72 KB
    const int SMEM2 = 2 * STG2 * 4;  // 72 KB
    cudaFuncSetAttribute(gemm1_mma, cudaFuncAttributeMaxDynamicSharedMemorySize, SMEM1);
    cudaFuncSetAttribute(gemm2_mma, cudaFuncAttributeMaxDynamicSharedMemorySize, SMEM2);

    // order: gemm2 is the 4th launch (profiled slot)
    convAQ_kernel<<<8448, 256>>>(normq, kfeat, queue);
    convP_kernel<<<dim3(32, 1024), 256>>>(qlp);
    gemm1_mma<<<dim3(8, 512), 256, SMEM1>>>();
    gemm2_mma<<<dim3(9, 4, 8), 256, SMEM2>>>();
    detect_kernel<<<1, 32>>>((const int*)qlabel);
    supcon_kernel<<<512, 256>>>(qlabel, target, knnk);
    invz_kernel<<<512, 256>>>();
    fcdc_kernel<<<512, 256>>>(qlog, target);
    finalize_kernel<<<1, 512>>>(out);
    (void)in_sizes; (void)n_in; (void)out_size;
}